// round 6
// baseline (speedup 1.0000x reference)
#include <cuda_runtime.h>

#define S   32768          // 32*32*32 spatial
#define NB  2              // batch
#define CIN 64
#define CM  32             // mid channels
#define KCH 216            // dynamic kernel channels
#define NG  8              // groups
#define CPG 8              // channels per group (64/8)

typedef unsigned long long u64;

// ---------------- f32x2 helpers ----------------
__device__ __forceinline__ u64 pk2(float a, float b) {
    u64 r; asm("mov.b64 %0,{%1,%2};" : "=l"(r) : "f"(a), "f"(b)); return r;
}
__device__ __forceinline__ void upk2(u64 v, float& a, float& b) {
    asm("mov.b64 {%0,%1},%2;" : "=f"(a), "=f"(b) : "l"(v));
}
__device__ __forceinline__ void fma2(u64& d, u64 a, u64 b) {
    asm("fma.rn.f32x2 %0,%1,%2,%0;" : "+l"(d) : "l"(a), "l"(b));
}
__device__ __forceinline__ void add2(u64& d, u64 a) {
    asm("add.rn.f32x2 %0,%1,%0;" : "+l"(d) : "l"(a));
}

// ---------------- scratch (device globals; allocation-free) ----------------
__device__ float g_a1[NB * CM  * S];   // cv1 out; later reused for cv3 out (a3)
__device__ float g_a2[NB * CM  * S];   // after dw5+bn
__device__ float g_wk[NB * KCH * S];   // cv4 output (pre-GN)
__device__ float g_y [NB * CIN * S];   // after SKA + bn + residual
__device__ float g_h [NB * 128 * S];   // FFN hidden
__device__ float g_sum[NB * NG];
__device__ float g_sq [NB * NG];
__device__ float g_mu [NB * NG];
__device__ float g_rstd[NB * NG];

// ---------------- k0: zero group stats ----------------
__global__ void k0_zero() {
    int i = threadIdx.x;
    if (i < NB * NG) { g_sum[i] = 0.f; g_sq[i] = 0.f; }
}

// ================= R3 KNOWN-PASSING FRONT HALF (verbatim) =================

// ---------------- k1: cv1 (64->32) + BN + ReLU ----------------
__global__ void k1_cv1(const float* __restrict__ x, const float* __restrict__ w1,
                       const float* __restrict__ s1, const float* __restrict__ b1) {
    __shared__ u64 ws[CM * CIN];     // packed {w,w}, 16KB
    int t = threadIdx.x;
    for (int i = t; i < CM * CIN; i += 128) { float w = w1[i]; ws[i] = pk2(w, w); }
    __syncthreads();

    int og = t >> 6, slot = t & 63;
    int pos = blockIdx.x * 256 + slot * 4;
    int b = pos >> 15, s = pos & (S - 1);

    u64 aL[16], aH[16];
#pragma unroll
    for (int o = 0; o < 16; o++) { aL[o] = 0ull; aH[o] = 0ull; }

    const float* xb = x + b * CIN * S + s;
    for (int c = 0; c < CIN; c++) {
        ulonglong2 xq = *(const ulonglong2*)(xb + c * S);
#pragma unroll
        for (int o = 0; o < 16; o++) {
            u64 wv = ws[(og * 16 + o) * CIN + c];
            fma2(aL[o], wv, xq.x);
            fma2(aH[o], wv, xq.y);
        }
    }
#pragma unroll
    for (int o = 0; o < 16; o++) {
        int oo = og * 16 + o;
        float sc = __ldg(s1 + oo), bb = __ldg(b1 + oo);
        float a0, a1v, a2v, a3v;
        upk2(aL[o], a0, a1v); upk2(aH[o], a2v, a3v);
        float4 r;
        r.x = fmaxf(a0  * sc + bb, 0.f);
        r.y = fmaxf(a1v * sc + bb, 0.f);
        r.z = fmaxf(a2v * sc + bb, 0.f);
        r.w = fmaxf(a3v * sc + bb, 0.f);
        *(float4*)(g_a1 + (b * CM + oo) * S + s) = r;
    }
}

// ---------------- k2: depthwise 5x5x5 (zero pad) + BN ----------------
__global__ void k2_dw5(const float* __restrict__ w2, const float* __restrict__ s2,
                       const float* __restrict__ b2) {
    int gid = blockIdx.x * blockDim.x + threadIdx.x;  // 0..65535
    int h = gid & 31;
    int d = (gid >> 5) & 31;
    int c = (gid >> 10) & 31;
    int b = gid >> 15;

    float acc[32];
#pragma unroll
    for (int w = 0; w < 32; w++) acc[w] = 0.f;

    const float* src = g_a1 + (b * CM + c) * S;
    const float* wc  = w2 + c * 125;

    for (int dd = 0; dd < 5; dd++) {
        int zd = d + dd - 2;
        if (zd < 0 || zd >= 32) continue;
        for (int dh = 0; dh < 5; dh++) {
            int zh = h + dh - 2;
            if (zh < 0 || zh >= 32) continue;
            const float* row = src + (zd * 32 + zh) * 32;
            float rw[32];
#pragma unroll
            for (int i = 0; i < 8; i++) {
                float4 v = *(const float4*)(row + i * 4);
                rw[i * 4 + 0] = v.x; rw[i * 4 + 1] = v.y;
                rw[i * 4 + 2] = v.z; rw[i * 4 + 3] = v.w;
            }
            const float* wr = wc + (dd * 5 + dh) * 5;
#pragma unroll
            for (int dw = 0; dw < 5; dw++) {
                float tap = wr[dw];
#pragma unroll
                for (int w = 0; w < 32; w++) {
                    int idx = w + dw - 2;
                    if (idx >= 0 && idx < 32) acc[w] += tap * rw[idx];
                }
            }
        }
    }
    float sc = s2[c], bi = b2[c];
    float* dst = g_a2 + (b * CM + c) * S + (d * 32 + h) * 32;
#pragma unroll
    for (int w = 0; w < 32; w++) dst[w] = acc[w] * sc + bi;
}

// ---------------- k3a: cv3 (32->32) + BN + ReLU -> g_a1 (reuse) ----------------
__global__ void k3a_cv3(const float* __restrict__ w3, const float* __restrict__ s3,
                        const float* __restrict__ b3) {
    __shared__ u64 ws[CM * CM];      // 8KB
    int t = threadIdx.x;
    for (int i = t; i < CM * CM; i += 128) { float w = w3[i]; ws[i] = pk2(w, w); }
    __syncthreads();

    int og = t >> 6, slot = t & 63;
    int pos = blockIdx.x * 256 + slot * 4;
    int b = pos >> 15, s = pos & (S - 1);

    u64 aL[16], aH[16];
#pragma unroll
    for (int o = 0; o < 16; o++) { aL[o] = 0ull; aH[o] = 0ull; }

    const float* xb = g_a2 + b * CM * S + s;
    for (int c = 0; c < CM; c++) {
        ulonglong2 xq = *(const ulonglong2*)(xb + c * S);
#pragma unroll
        for (int o = 0; o < 16; o++) {
            u64 wv = ws[(og * 16 + o) * CM + c];
            fma2(aL[o], wv, xq.x);
            fma2(aH[o], wv, xq.y);
        }
    }
#pragma unroll
    for (int o = 0; o < 16; o++) {
        int oo = og * 16 + o;
        float sc = __ldg(s3 + oo), bb = __ldg(b3 + oo);
        float a0, a1v, a2v, a3v;
        upk2(aL[o], a0, a1v); upk2(aH[o], a2v, a3v);
        float4 r;
        r.x = fmaxf(a0  * sc + bb, 0.f);
        r.y = fmaxf(a1v * sc + bb, 0.f);
        r.z = fmaxf(a2v * sc + bb, 0.f);
        r.w = fmaxf(a3v * sc + bb, 0.f);
        *(float4*)(g_a1 + (b * CM + oo) * S + s) = r;
    }
}

// ---------------- k3b: cv4 (32->216) + b4 + GN partial sums (R3 version) ----
__global__ void k3b_cv4(const float* __restrict__ w4, const float* __restrict__ b4) {
    extern __shared__ u64 sm[];
    u64* w4p = sm;                 // 216*32
    u64* b4p = sm + KCH * CM;      // 216
    int t = threadIdx.x;
    for (int i = t; i < KCH * CM; i += 128) { float w = w4[i]; w4p[i] = pk2(w, w); }
    for (int i = t; i < KCH; i += 128)      { float w = b4[i]; b4p[i] = pk2(w, w); }
    __shared__ float redsum[NG], redsq[NG];
    if (t < NG) { redsum[t] = 0.f; redsq[t] = 0.f; }
    __syncthreads();

    int g = t >> 4, slot = t & 15;
    int pos = blockIdx.x * 64 + slot * 4;
    int b = pos >> 15, s = pos & (S - 1);

    ulonglong2 aq[CM];
    const float* src = g_a1 + b * CM * S + s;
#pragma unroll
    for (int c = 0; c < CM; c++) aq[c] = *(const ulonglong2*)(src + c * S);

    u64 suL = 0ull, suH = 0ull, sqL = 0ull, sqH = 0ull;
    float* dst = g_wk + b * KCH * S + s;
    for (int k = 0; k < 27; k++) {
        int kk = g * 27 + k;
        u64 L = b4p[kk], H = b4p[kk];
        const u64* wr = w4p + kk * CM;
#pragma unroll
        for (int c = 0; c < CM; c++) {
            u64 wv = wr[c];
            fma2(L, wv, aq[c].x);
            fma2(H, wv, aq[c].y);
        }
        ulonglong2 o; o.x = L; o.y = H;
        *(ulonglong2*)(dst + kk * S) = o;
        add2(suL, L); add2(suH, H);
        fma2(sqL, L, L); fma2(sqH, H, H);
    }
    float x0, x1, x2, x3;
    upk2(suL, x0, x1); upk2(suH, x2, x3);
    float su = x0 + x1 + x2 + x3;
    upk2(sqL, x0, x1); upk2(sqH, x2, x3);
    float sq = x0 + x1 + x2 + x3;
    atomicAdd(&redsum[g], su);
    atomicAdd(&redsq[g], sq);
    __syncthreads();
    if (t < NG) {
        atomicAdd(&g_sum[b * NG + t], redsum[t]);
        atomicAdd(&g_sq [b * NG + t], redsq[t]);
    }
}

// ---------------- k4: finalize GN stats ----------------
__global__ void k4_stats() {
    int i = threadIdx.x;
    if (i < NB * NG) {
        float n  = 27.f * (float)S;
        float mu = g_sum[i] / n;
        float var = g_sq[i] / n - mu * mu;
        g_mu[i] = mu;
        g_rstd[i] = rsqrtf(var + 1e-5f);
    }
}

// ---------------- k5: GN affine + SKA (circular) + BN + residual -> y ------
__global__ void k5_ska(const float* __restrict__ x,
                       const float* __restrict__ gn_g, const float* __restrict__ gn_b,
                       const float* __restrict__ bn_s, const float* __restrict__ bn_b) {
    int gid = blockIdx.x * blockDim.x + threadIdx.x;   // 0 .. 131071
    int wq = gid & 7;
    int h  = (gid >> 3) & 31;
    int d  = (gid >> 8) & 31;
    int g  = (gid >> 13) & 7;
    int b  = gid >> 16;
    int w0 = wq * 4;
    int sbase = (d * 32 + h) * 32 + w0;

    float mu = g_mu[b * NG + g], rs = g_rstd[b * NG + g];

    u64 kvL[27], kvH[27];
    const float* wsrc = g_wk + (b * KCH + g * 27) * S + sbase;
#pragma unroll
    for (int k = 0; k < 27; k++) {
        float4 q = *(const float4*)(wsrc + k * S);
        int ch = g * 27 + k;
        float gg = __ldg(gn_g + ch) * rs;
        float bb = __ldg(gn_b + ch) - mu * gg;
        kvL[k] = pk2(q.x * gg + bb, q.y * gg + bb);
        kvH[k] = pk2(q.z * gg + bb, q.w * gg + bb);
    }

    const float* xg = x + (b * CIN + g * CPG) * S;
    float* yg = g_y + (b * CIN + g * CPG) * S;

    for (int c = 0; c < CPG; c++) {
        const float* xc = xg + c * S;
        u64 aL = 0ull, aH = 0ull;
        int k = 0;
#pragma unroll
        for (int di = -1; di <= 1; di++) {
            int zd = (d + di) & 31;
#pragma unroll
            for (int hi = -1; hi <= 1; hi++) {
                int zh = (h + hi) & 31;
                const float* row = xc + (zd * 32 + zh) * 32;
                float4 mid = *(const float4*)(row + w0);
                float v0 = row[(w0 - 1) & 31];
                float v5 = row[(w0 + 4) & 31];
                u64 p01 = pk2(v0,    mid.x);
                u64 p12 = pk2(mid.x, mid.y);
                u64 p23 = pk2(mid.y, mid.z);
                u64 p34 = pk2(mid.z, mid.w);
                u64 p45 = pk2(mid.w, v5);
                fma2(aL, kvL[k + 0], p01); fma2(aH, kvH[k + 0], p23);
                fma2(aL, kvL[k + 1], p12); fma2(aH, kvH[k + 1], p34);
                fma2(aL, kvL[k + 2], p23); fma2(aH, kvH[k + 2], p45);
                k += 3;
            }
        }
        float a0, a1v, a2v, a3v;
        upk2(aL, a0, a1v); upk2(aH, a2v, a3v);
        int ch = g * CPG + c;
        float bs_ = __ldg(bn_s + ch), bb_ = __ldg(bn_b + ch);
        float4 xq = *(const float4*)(xc + sbase);
        float4 r;
        r.x = a0  * bs_ + bb_ + xq.x;
        r.y = a1v * bs_ + bb_ + xq.y;
        r.z = a2v * bs_ + bb_ + xq.z;
        r.w = a3v * bs_ + bb_ + xq.w;
        *(float4*)(yg + c * S + sbase) = r;
    }
}

// ================= NEW BACK HALF (under test) =================

// ---------------- k6a: pw1 (64->128) + BN + ReLU ----------------
// block 512 = 16 warps (one og each); lane = position-pair (64 pos/block).
__global__ void __launch_bounds__(512) k6a_pw1(
        const float* __restrict__ w, const float* __restrict__ sc,
        const float* __restrict__ bi) {
    extern __shared__ u64 sm[];
    u64* wp = sm;              // 128*64 = 8192
    u64* yp = sm + 8192;       // 64 c x 32 pairs = 2048
    int t = threadIdx.x;
    for (int i = t; i < 8192; i += 512) { float v = w[i]; wp[i] = pk2(v, v); }

    int pos0 = blockIdx.x * 64;
    int b = pos0 >> 15, s = pos0 & (S - 1);
    for (int i = t; i < 2048; i += 512) {
        int c = i >> 5, j = i & 31;
        yp[i] = *(const u64*)(g_y + (b * CIN + c) * S + s + 2 * j);
    }
    __syncthreads();

    int og = t >> 5, lane = t & 31;
    u64 acc[8];
#pragma unroll
    for (int o = 0; o < 8; o++) acc[o] = 0ull;

#pragma unroll 4
    for (int c = 0; c < CIN; c++) {
        u64 yq = yp[c * 32 + lane];
#pragma unroll
        for (int o = 0; o < 8; o++) fma2(acc[o], wp[(og * 8 + o) * CIN + c], yq);
    }
#pragma unroll
    for (int o = 0; o < 8; o++) {
        int oo = og * 8 + o;
        float scv = __ldg(sc + oo), biv = __ldg(bi + oo);
        float a, bq; upk2(acc[o], a, bq);
        u64 r = pk2(fmaxf(a * scv + biv, 0.f), fmaxf(bq * scv + biv, 0.f));
        *(u64*)(g_h + (b * 128 + oo) * S + s + 2 * lane) = r;
    }
}

// ---------------- k6b: pw2 (128->64) + BN + add y -> out ----------------
// block 512 = 16 warps: og = w&7, posset = w>>3; 128 pos/block.
__global__ void __launch_bounds__(512) k6b_pw2(
        const float* __restrict__ w, const float* __restrict__ sc,
        const float* __restrict__ bi, float* __restrict__ out) {
    extern __shared__ u64 sm[];
    u64* wp = sm;              // 64*128 = 8192 (straight copy, [o][c])
    u64* hp = sm + 8192;       // 128 c x 64 pairs = 8192
    int t = threadIdx.x;
    for (int i = t; i < 8192; i += 512) { float v = w[i]; wp[i] = pk2(v, v); }

    int pos0 = blockIdx.x * 128;
    int b = pos0 >> 15, s = pos0 & (S - 1);
    for (int i = t; i < 8192; i += 512) {
        int c = i >> 6, j = i & 63;
        hp[i] = *(const u64*)(g_h + (b * 128 + c) * S + s + 2 * j);
    }
    __syncthreads();

    int warp = t >> 5, lane = t & 31;
    int og = warp & 7, pset = warp >> 3;
    int pair = pset * 32 + lane;               // 0..63

    u64 acc[8];
#pragma unroll
    for (int o = 0; o < 8; o++) acc[o] = 0ull;

#pragma unroll 4
    for (int c = 0; c < 128; c++) {
        u64 hq = hp[c * 64 + pair];
#pragma unroll
        for (int o = 0; o < 8; o++) fma2(acc[o], wp[(og * 8 + o) * 128 + c], hq);
    }
#pragma unroll
    for (int o = 0; o < 8; o++) {
        int oo = og * 8 + o;
        float scv = __ldg(sc + oo), biv = __ldg(bi + oo);
        float a, bq; upk2(acc[o], a, bq);
        float y0, y1;
        upk2(*(const u64*)(g_y + (b * CIN + oo) * S + s + 2 * pair), y0, y1);
        u64 r = pk2(y0 + a * scv + biv, y1 + bq * scv + biv);
        *(u64*)(out + (b * CIN + oo) * S + s + 2 * pair) = r;
    }
}

// ---------------- launcher ----------------
extern "C" void kernel_launch(void* const* d_in, const int* in_sizes, int n_in,
                              void* d_out, int out_size) {
    const float* x     = (const float*)d_in[0];
    const float* w1    = (const float*)d_in[1];
    const float* s1    = (const float*)d_in[2];
    const float* b1    = (const float*)d_in[3];
    const float* w2    = (const float*)d_in[4];
    const float* s2    = (const float*)d_in[5];
    const float* b2    = (const float*)d_in[6];
    const float* w3    = (const float*)d_in[7];
    const float* s3    = (const float*)d_in[8];
    const float* b3    = (const float*)d_in[9];
    const float* w4    = (const float*)d_in[10];
    const float* b4    = (const float*)d_in[11];
    const float* gn_g  = (const float*)d_in[12];
    const float* gn_b  = (const float*)d_in[13];
    const float* bn_s  = (const float*)d_in[14];
    const float* bn_b  = (const float*)d_in[15];
    const float* pw1_w = (const float*)d_in[16];
    const float* pw1_s = (const float*)d_in[17];
    const float* pw1_b = (const float*)d_in[18];
    const float* pw2_w = (const float*)d_in[19];
    const float* pw2_s = (const float*)d_in[20];
    const float* pw2_b = (const float*)d_in[21];
    float* out = (float*)d_out;

    const int smem_k3b = (KCH * CM + KCH) * 8;       // R3 layout
    const int smem_k6a = (8192 + 2048) * 8;          // 80 KB
    const int smem_k6b = (8192 + 8192) * 8;          // 128 KB
    cudaFuncSetAttribute(k3b_cv4, cudaFuncAttributeMaxDynamicSharedMemorySize, smem_k3b);
    cudaFuncSetAttribute(k6a_pw1, cudaFuncAttributeMaxDynamicSharedMemorySize, smem_k6a);
    cudaFuncSetAttribute(k6b_pw2, cudaFuncAttributeMaxDynamicSharedMemorySize, smem_k6b);

    k0_zero <<<1, 32>>>();
    k1_cv1  <<<256, 128>>>(x, w1, s1, b1);               // R3
    k2_dw5  <<<256, 256>>>(w2, s2, b2);                  // R3
    k3a_cv3 <<<256, 128>>>(w3, s3, b3);                  // R3
    k3b_cv4 <<<1024, 128, smem_k3b>>>(w4, b4);           // R3
    k4_stats<<<1, 32>>>();
    k5_ska  <<<1024, 128>>>(x, gn_g, gn_b, bn_s, bn_b);  // R3
    k6a_pw1 <<<1024, 512, smem_k6a>>>(pw1_w, pw1_s, pw1_b);   // NEW
    k6b_pw2 <<<512, 512, smem_k6b>>>(pw2_w, pw2_s, pw2_b, out); // NEW
}

// round 7
// speedup vs baseline: 1.0212x; 1.0212x over previous
#include <cuda_runtime.h>

#define S   32768          // 32*32*32 spatial
#define NB  2              // batch
#define CIN 64
#define CM  32             // mid channels
#define KCH 216            // dynamic kernel channels
#define NG  8              // groups
#define CPG 8              // channels per group (64/8)

typedef unsigned long long u64;

// ---------------- f32x2 helpers ----------------
__device__ __forceinline__ u64 pk2(float a, float b) {
    u64 r; asm("mov.b64 %0,{%1,%2};" : "=l"(r) : "f"(a), "f"(b)); return r;
}
__device__ __forceinline__ void upk2(u64 v, float& a, float& b) {
    asm("mov.b64 {%0,%1},%2;" : "=f"(a), "=f"(b) : "l"(v));
}
__device__ __forceinline__ void fma2(u64& d, u64 a, u64 b) {
    asm("fma.rn.f32x2 %0,%1,%2,%0;" : "+l"(d) : "l"(a), "l"(b));
}

// ---------------- scratch (device globals; allocation-free) ----------------
__device__ float g_a1[NB * CM  * S];   // cv1 out; later reused for cv3 out (a3)
__device__ float g_a2[NB * CM  * S];   // after dw5+bn
__device__ float g_wk[NB * KCH * S];   // cv4 output (pre-GN)
__device__ float g_y [NB * CIN * S];   // after SKA + bn + residual
__device__ float g_h [NB * 128 * S];   // FFN hidden
__device__ float g_sum[NB * NG];
__device__ float g_sq [NB * NG];
__device__ float g_mu [NB * NG];
__device__ float g_rstd[NB * NG];

// ---------------- k0: zero group stats ----------------
__global__ void k0_zero() {
    int i = threadIdx.x;
    if (i < NB * NG) { g_sum[i] = 0.f; g_sq[i] = 0.f; }
}

// ---------------- cv body: K->32 1x1 conv + BN + ReLU ----------------
// block 256 = 8 warps; warp = og (4 ogs x 2 position-sets); thread = 2 pos x 8 out.
// NOTE: scratch globals must be referenced from DEVICE code (wrappers below),
// never passed as kernel args from the host (device-symbol shadow bug, R4-R6).
template<int K>
__device__ __forceinline__ void cv_body(
        const float* __restrict__ in, const float* __restrict__ w,
        const float* __restrict__ sc, const float* __restrict__ bi,
        float* __restrict__ outbuf) {
    __shared__ u64 ws[32 * K];
    int t = threadIdx.x;
    for (int i = t; i < 32 * K; i += 256) { float v = w[i]; ws[i] = pk2(v, v); }
    __syncthreads();

    int warp = t >> 5, lane = t & 31;
    int og = warp & 3, pset = warp >> 2;
    int pair = pset * 32 + lane;                 // 0..63
    int pos0 = blockIdx.x * 128 + pair * 2;
    int b = pos0 >> 15, s = pos0 & (S - 1);

    u64 acc[8];
#pragma unroll
    for (int o = 0; o < 8; o++) acc[o] = 0ull;

    const float* ib = in + b * K * S + s;
#pragma unroll 4
    for (int c = 0; c < K; c++) {
        u64 xq = *(const u64*)(ib + c * S);
#pragma unroll
        for (int o = 0; o < 8; o++) fma2(acc[o], ws[(og * 8 + o) * K + c], xq);
    }
#pragma unroll
    for (int o = 0; o < 8; o++) {
        int oo = og * 8 + o;
        float scv = __ldg(sc + oo), biv = __ldg(bi + oo);
        float a, bq; upk2(acc[o], a, bq);
        u64 r = pk2(fmaxf(a * scv + biv, 0.f), fmaxf(bq * scv + biv, 0.f));
        *(u64*)(outbuf + (b * CM + oo) * S + s) = r;
    }
}

__global__ void __launch_bounds__(256) k1_cv1(
        const float* __restrict__ x, const float* __restrict__ w1,
        const float* __restrict__ s1, const float* __restrict__ b1) {
    cv_body<64>(x, w1, s1, b1, g_a1);          // g_a1 resolved device-side
}

__global__ void __launch_bounds__(256) k3a_cv3(
        const float* __restrict__ w3, const float* __restrict__ s3,
        const float* __restrict__ b3) {
    cv_body<32>(g_a2, w3, s3, b3, g_a1);       // device-side globals
}

// ---------------- k2: depthwise 5x5x5 (zero pad) + BN, f32x2 ----------------
// block 128 = one (b,c,d) slab: 32 h x 4 wq; thread = 8 consecutive w outputs.
__global__ void __launch_bounds__(128) k2_dw5(
        const float* __restrict__ w2, const float* __restrict__ s2,
        const float* __restrict__ b2) {
    int blk = blockIdx.x;            // (b*32+c)*32+d
    int d = blk & 31;
    int c = (blk >> 5) & 31;
    int b = blk >> 10;
    int t = threadIdx.x;
    int wq = t & 3, h = t >> 2;
    int w0 = wq * 8;

    const float* src = g_a1 + (b * CM + c) * S;
    const float* wc  = w2 + c * 125;
    const float4 zero4 = make_float4(0.f, 0.f, 0.f, 0.f);

    u64 acc[4];
#pragma unroll
    for (int m = 0; m < 4; m++) acc[m] = 0ull;

    for (int dd = 0; dd < 5; dd++) {
        int zd = d + dd - 2;
        if ((unsigned)zd >= 32u) continue;
        for (int dh = 0; dh < 5; dh++) {
            int zh = h + dh - 2;
            if ((unsigned)zh >= 32u) continue;
            const float* row = src + (zd * 32 + zh) * 32;
            float4 f0 = (wq > 0) ? *(const float4*)(row + w0 - 4) : zero4;
            float4 f1 = *(const float4*)(row + w0);
            float4 f2 = *(const float4*)(row + w0 + 4);
            float4 f3 = (wq < 3) ? *(const float4*)(row + w0 + 8) : zero4;
            u64 A0 = pk2(f0.z, f0.w), A1 = pk2(f1.x, f1.y), A2 = pk2(f1.z, f1.w);
            u64 A3 = pk2(f2.x, f2.y), A4 = pk2(f2.z, f2.w), A5 = pk2(f3.x, f3.y);
            u64 M0 = pk2(f0.w, f1.x), M1 = pk2(f1.y, f1.z), M2 = pk2(f1.w, f2.x);
            u64 M3 = pk2(f2.y, f2.z), M4 = pk2(f2.w, f3.x);
            const float* wr = wc + (dd * 5 + dh) * 5;
            u64 T0 = pk2(wr[0], wr[0]), T1 = pk2(wr[1], wr[1]), T2 = pk2(wr[2], wr[2]);
            u64 T3 = pk2(wr[3], wr[3]), T4 = pk2(wr[4], wr[4]);
            fma2(acc[0], T0, A0); fma2(acc[0], T1, M0); fma2(acc[0], T2, A1);
            fma2(acc[0], T3, M1); fma2(acc[0], T4, A2);
            fma2(acc[1], T0, A1); fma2(acc[1], T1, M1); fma2(acc[1], T2, A2);
            fma2(acc[1], T3, M2); fma2(acc[1], T4, A3);
            fma2(acc[2], T0, A2); fma2(acc[2], T1, M2); fma2(acc[2], T2, A3);
            fma2(acc[2], T3, M3); fma2(acc[2], T4, A4);
            fma2(acc[3], T0, A3); fma2(acc[3], T1, M3); fma2(acc[3], T2, A4);
            fma2(acc[3], T3, M4); fma2(acc[3], T4, A5);
        }
    }
    float scv = s2[c], biv = b2[c];
    float* dst = g_a2 + (b * CM + c) * S + (d * 32 + h) * 32 + w0;
#pragma unroll
    for (int m = 0; m < 4; m++) {
        float a, bb; upk2(acc[m], a, bb);
        *(u64*)(dst + 2 * m) = pk2(a * scv + biv, bb * scv + biv);
    }
}

// ---------------- k3b: cv4 (32->216) + b4 + GN partial sums ----------------
// block 864 = 27 warps (one og of 8 channels each); lane = position-pair (64 pos/block).
__global__ void __launch_bounds__(864, 1) k3b_cv4(
        const float* __restrict__ w4, const float* __restrict__ b4) {
    extern __shared__ u64 sm[];
    u64* wp = sm;              // 216*32 = 6912
    u64* ap = sm + 6912;       // 32 c x 32 pairs = 1024
    __shared__ float redsum[NG], redsq[NG];
    int t = threadIdx.x;
    for (int i = t; i < KCH * CM; i += 864) { float v = w4[i]; wp[i] = pk2(v, v); }
    if (t < NG) { redsum[t] = 0.f; redsq[t] = 0.f; }

    int pos0 = blockIdx.x * 64;
    int b = pos0 >> 15, s = pos0 & (S - 1);
    for (int i = t; i < 1024; i += 864) {
        int c = i >> 5, j = i & 31;
        ap[i] = *(const u64*)(g_a1 + (b * CM + c) * S + s + 2 * j);
    }
    __syncthreads();

    int og = t >> 5, lane = t & 31;   // og = 0..26
    u64 acc[8];
#pragma unroll
    for (int o = 0; o < 8; o++) { float bv = __ldg(b4 + og * 8 + o); acc[o] = pk2(bv, bv); }

#pragma unroll 4
    for (int c = 0; c < CM; c++) {
        u64 aq = ap[c * 32 + lane];
#pragma unroll
        for (int o = 0; o < 8; o++) fma2(acc[o], wp[(og * 8 + o) * CM + c], aq);
    }

    int kk0 = og * 8;
    int g0 = kk0 / 27;
    int brk = (g0 + 1) * 27 - kk0;       // o < brk -> group g0, else g0+1
    float su0 = 0.f, sq0 = 0.f, su1 = 0.f, sq1 = 0.f;
#pragma unroll
    for (int o = 0; o < 8; o++) {
        int kk = kk0 + o;
        *(u64*)(g_wk + (b * KCH + kk) * S + s + 2 * lane) = acc[o];
        float a, bv; upk2(acc[o], a, bv);
        float ss = a + bv, qq = a * a + bv * bv;
        if (o < brk) { su0 += ss; sq0 += qq; } else { su1 += ss; sq1 += qq; }
    }
#pragma unroll
    for (int off = 16; off; off >>= 1) {
        su0 += __shfl_down_sync(0xffffffffu, su0, off);
        sq0 += __shfl_down_sync(0xffffffffu, sq0, off);
        su1 += __shfl_down_sync(0xffffffffu, su1, off);
        sq1 += __shfl_down_sync(0xffffffffu, sq1, off);
    }
    if (lane == 0) {
        atomicAdd(&redsum[g0], su0); atomicAdd(&redsq[g0], sq0);
        if (brk < 8) { atomicAdd(&redsum[g0 + 1], su1); atomicAdd(&redsq[g0 + 1], sq1); }
    }
    __syncthreads();
    if (t < NG) {
        atomicAdd(&g_sum[b * NG + t], redsum[t]);
        atomicAdd(&g_sq [b * NG + t], redsq[t]);
    }
}

// ---------------- k4: finalize GN stats ----------------
__global__ void k4_stats() {
    int i = threadIdx.x;
    if (i < NB * NG) {
        float n  = 27.f * (float)S;
        float mu = g_sum[i] / n;
        float var = g_sq[i] / n - mu * mu;
        g_mu[i] = mu;
        g_rstd[i] = rsqrtf(var + 1e-5f);
    }
}

// ---------------- k5: GN affine + SKA (circular) + BN + residual -> y ------
__global__ void k5_ska(const float* __restrict__ x,
                       const float* __restrict__ gn_g, const float* __restrict__ gn_b,
                       const float* __restrict__ bn_s, const float* __restrict__ bn_b) {
    int gid = blockIdx.x * blockDim.x + threadIdx.x;   // 0 .. 131071
    int wq = gid & 7;
    int h  = (gid >> 3) & 31;
    int d  = (gid >> 8) & 31;
    int g  = (gid >> 13) & 7;
    int b  = gid >> 16;
    int w0 = wq * 4;
    int sbase = (d * 32 + h) * 32 + w0;

    float mu = g_mu[b * NG + g], rs = g_rstd[b * NG + g];

    u64 kvL[27], kvH[27];
    const float* wsrc = g_wk + (b * KCH + g * 27) * S + sbase;
#pragma unroll
    for (int k = 0; k < 27; k++) {
        float4 q = *(const float4*)(wsrc + k * S);
        int ch = g * 27 + k;
        float gg = __ldg(gn_g + ch) * rs;
        float bb = __ldg(gn_b + ch) - mu * gg;
        kvL[k] = pk2(q.x * gg + bb, q.y * gg + bb);
        kvH[k] = pk2(q.z * gg + bb, q.w * gg + bb);
    }

    const float* xg = x + (b * CIN + g * CPG) * S;
    float* yg = g_y + (b * CIN + g * CPG) * S;

    for (int c = 0; c < CPG; c++) {
        const float* xc = xg + c * S;
        u64 aL = 0ull, aH = 0ull;
        int k = 0;
#pragma unroll
        for (int di = -1; di <= 1; di++) {
            int zd = (d + di) & 31;
#pragma unroll
            for (int hi = -1; hi <= 1; hi++) {
                int zh = (h + hi) & 31;
                const float* row = xc + (zd * 32 + zh) * 32;
                float4 mid = *(const float4*)(row + w0);
                float v0 = row[(w0 - 1) & 31];
                float v5 = row[(w0 + 4) & 31];
                u64 p01 = pk2(v0,    mid.x);
                u64 p12 = pk2(mid.x, mid.y);
                u64 p23 = pk2(mid.y, mid.z);
                u64 p34 = pk2(mid.z, mid.w);
                u64 p45 = pk2(mid.w, v5);
                fma2(aL, kvL[k + 0], p01); fma2(aH, kvH[k + 0], p23);
                fma2(aL, kvL[k + 1], p12); fma2(aH, kvH[k + 1], p34);
                fma2(aL, kvL[k + 2], p23); fma2(aH, kvH[k + 2], p45);
                k += 3;
            }
        }
        float a0, a1v, a2v, a3v;
        upk2(aL, a0, a1v); upk2(aH, a2v, a3v);
        int ch = g * CPG + c;
        float bs_ = __ldg(bn_s + ch), bb_ = __ldg(bn_b + ch);
        float4 xq = *(const float4*)(xc + sbase);
        float4 r;
        r.x = a0  * bs_ + bb_ + xq.x;
        r.y = a1v * bs_ + bb_ + xq.y;
        r.z = a2v * bs_ + bb_ + xq.z;
        r.w = a3v * bs_ + bb_ + xq.w;
        *(float4*)(yg + c * S + sbase) = r;
    }
}

// ---------------- k6a: pw1 (64->128) + BN + ReLU ----------------
// block 512 = 16 warps, warp = og (8 outputs); thread = 4 pos (pairs lane, lane+32).
// y read via LDG (all warps hit the same tile in L1); weights in 64KB smem.
__global__ void __launch_bounds__(512) k6a_pw1(
        const float* __restrict__ w, const float* __restrict__ sc,
        const float* __restrict__ bi) {
    extern __shared__ u64 sm[];
    u64* wp = sm;              // 128*64 = 8192 u64 = 64KB
    int t = threadIdx.x;
    for (int i = t; i < 8192; i += 512) { float v = w[i]; wp[i] = pk2(v, v); }
    __syncthreads();

    int og = t >> 5, lane = t & 31;     // og 0..15
    int pos0 = blockIdx.x * 128;        // grid 512
    int b = pos0 >> 15, s = pos0 & (S - 1);

    u64 accA[8], accB[8];
#pragma unroll
    for (int o = 0; o < 8; o++) { accA[o] = 0ull; accB[o] = 0ull; }

    const float* yb = g_y + b * CIN * S + s;
#pragma unroll 4
    for (int c = 0; c < CIN; c++) {
        const float* yr = yb + c * S;
        u64 yqA = *(const u64*)(yr + 2 * lane);
        u64 yqB = *(const u64*)(yr + 64 + 2 * lane);
#pragma unroll
        for (int o = 0; o < 8; o++) {
            u64 wv = wp[(og * 8 + o) * CIN + c];
            fma2(accA[o], wv, yqA);
            fma2(accB[o], wv, yqB);
        }
    }
#pragma unroll
    for (int o = 0; o < 8; o++) {
        int oo = og * 8 + o;
        float scv = __ldg(sc + oo), biv = __ldg(bi + oo);
        float a, bq;
        float* hb = g_h + (b * 128 + oo) * S + s;
        upk2(accA[o], a, bq);
        *(u64*)(hb + 2 * lane) = pk2(fmaxf(a * scv + biv, 0.f), fmaxf(bq * scv + biv, 0.f));
        upk2(accB[o], a, bq);
        *(u64*)(hb + 64 + 2 * lane) = pk2(fmaxf(a * scv + biv, 0.f), fmaxf(bq * scv + biv, 0.f));
    }
}

// ---------------- k6b: pw2 (128->64) + BN + add y -> out ----------------
// block 512 = 16 warps: og = warp&7, pset = warp>>3; thread = 4 pos; 256 pos/block.
__global__ void __launch_bounds__(512) k6b_pw2(
        const float* __restrict__ w, const float* __restrict__ sc,
        const float* __restrict__ bi, float* __restrict__ out) {
    extern __shared__ u64 sm[];
    u64* wp = sm;              // 64*128 = 8192 u64 = 64KB ([o][c] straight copy)
    int t = threadIdx.x;
    for (int i = t; i < 8192; i += 512) { float v = w[i]; wp[i] = pk2(v, v); }
    __syncthreads();

    int warp = t >> 5, lane = t & 31;
    int og = warp & 7, pset = warp >> 3;
    int p0 = pset * 64 + lane;           // pairs p0, p0+32
    int pos0 = blockIdx.x * 256;         // grid 256
    int b = pos0 >> 15, s = pos0 & (S - 1);

    u64 accA[8], accB[8];
#pragma unroll
    for (int o = 0; o < 8; o++) { accA[o] = 0ull; accB[o] = 0ull; }

    const float* hb = g_h + b * 128 * S + s;
#pragma unroll 4
    for (int c = 0; c < 128; c++) {
        const float* hr = hb + c * S;
        u64 hqA = *(const u64*)(hr + 2 * p0);
        u64 hqB = *(const u64*)(hr + 2 * p0 + 64);
#pragma unroll
        for (int o = 0; o < 8; o++) {
            u64 wv = wp[(og * 8 + o) * 128 + c];
            fma2(accA[o], wv, hqA);
            fma2(accB[o], wv, hqB);
        }
    }
#pragma unroll
    for (int o = 0; o < 8; o++) {
        int oo = og * 8 + o;
        float scv = __ldg(sc + oo), biv = __ldg(bi + oo);
        const float* yb = g_y + (b * CIN + oo) * S + s;
        float* ob = out + (b * CIN + oo) * S + s;
        float a, bq, y0, y1;
        upk2(accA[o], a, bq);
        upk2(*(const u64*)(yb + 2 * p0), y0, y1);
        *(u64*)(ob + 2 * p0) = pk2(y0 + a * scv + biv, y1 + bq * scv + biv);
        upk2(accB[o], a, bq);
        upk2(*(const u64*)(yb + 2 * p0 + 64), y0, y1);
        *(u64*)(ob + 2 * p0 + 64) = pk2(y0 + a * scv + biv, y1 + bq * scv + biv);
    }
}

// ---------------- launcher ----------------
extern "C" void kernel_launch(void* const* d_in, const int* in_sizes, int n_in,
                              void* d_out, int out_size) {
    const float* x     = (const float*)d_in[0];
    const float* w1    = (const float*)d_in[1];
    const float* s1    = (const float*)d_in[2];
    const float* b1    = (const float*)d_in[3];
    const float* w2    = (const float*)d_in[4];
    const float* s2    = (const float*)d_in[5];
    const float* b2    = (const float*)d_in[6];
    const float* w3    = (const float*)d_in[7];
    const float* s3    = (const float*)d_in[8];
    const float* b3    = (const float*)d_in[9];
    const float* w4    = (const float*)d_in[10];
    const float* b4    = (const float*)d_in[11];
    const float* gn_g  = (const float*)d_in[12];
    const float* gn_b  = (const float*)d_in[13];
    const float* bn_s  = (const float*)d_in[14];
    const float* bn_b  = (const float*)d_in[15];
    const float* pw1_w = (const float*)d_in[16];
    const float* pw1_s = (const float*)d_in[17];
    const float* pw1_b = (const float*)d_in[18];
    const float* pw2_w = (const float*)d_in[19];
    const float* pw2_s = (const float*)d_in[20];
    const float* pw2_b = (const float*)d_in[21];
    float* out = (float*)d_out;

    const int smem_k3b = (KCH * CM + 1024) * 8;      // 63.5 KB
    const int smem_k6  = 8192 * 8;                   // 64 KB
    cudaFuncSetAttribute(k3b_cv4, cudaFuncAttributeMaxDynamicSharedMemorySize, smem_k3b);
    cudaFuncSetAttribute(k6a_pw1, cudaFuncAttributeMaxDynamicSharedMemorySize, smem_k6);
    cudaFuncSetAttribute(k6b_pw2, cudaFuncAttributeMaxDynamicSharedMemorySize, smem_k6);

    k0_zero <<<1, 32>>>();
    k1_cv1  <<<512, 256>>>(x, w1, s1, b1);           // 128 pos/block
    k2_dw5  <<<2048, 128>>>(w2, s2, b2);
    k3a_cv3 <<<512, 256>>>(w3, s3, b3);
    k3b_cv4 <<<1024, 864, smem_k3b>>>(w4, b4);
    k4_stats<<<1, 32>>>();
    k5_ska  <<<1024, 128>>>(x, gn_g, gn_b, bn_s, bn_b);
    k6a_pw1 <<<512, 512, smem_k6>>>(pw1_w, pw1_s, pw1_b);      // 128 pos/block
    k6b_pw2 <<<256, 512, smem_k6>>>(pw2_w, pw2_s, pw2_b, out); // 256 pos/block
}

// round 8
// speedup vs baseline: 1.1253x; 1.1019x over previous
#include <cuda_runtime.h>

#define S   32768          // 32*32*32 spatial
#define NB  2              // batch
#define CIN 64
#define CM  32             // mid channels
#define KCH 216            // dynamic kernel channels
#define NG  8              // groups
#define CPG 8              // channels per group (64/8)

typedef unsigned long long u64;

// ---------------- f32x2 helpers ----------------
__device__ __forceinline__ u64 pk2(float a, float b) {
    u64 r; asm("mov.b64 %0,{%1,%2};" : "=l"(r) : "f"(a), "f"(b)); return r;
}
__device__ __forceinline__ void upk2(u64 v, float& a, float& b) {
    asm("mov.b64 {%0,%1},%2;" : "=f"(a), "=f"(b) : "l"(v));
}
__device__ __forceinline__ void fma2(u64& d, u64 a, u64 b) {
    asm("fma.rn.f32x2 %0,%1,%2,%0;" : "+l"(d) : "l"(a), "l"(b));
}

// ---------------- scratch (device globals; allocation-free) ----------------
__device__ float g_a1[NB * CM  * S];   // cv1 out; later reused for cv3 out (a3)
__device__ float g_a2[NB * CM  * S];   // after dw5+bn
__device__ float g_wk[NB * KCH * S];   // cv4 output (pre-GN)
__device__ float g_y [NB * CIN * S];   // after SKA + bn + residual
__device__ float g_h [NB * 128 * S];   // FFN hidden
__device__ float g_sum[NB * NG];       // zero-init; k4 re-zeros after use
__device__ float g_sq [NB * NG];
__device__ float g_mu [NB * NG];
__device__ float g_rstd[NB * NG];

// ---------------- cv body: K->32 1x1 conv + BN + ReLU ----------------
// block 256 = 8 warps: og = warp&1 (16 outs), pset = warp>>1 (4 sets x 32 lanes).
// Weights in smem as [c][o] so per-c weights are LDS.128-contiguous.
template<int K>
__device__ __forceinline__ void cv_body(
        const float* __restrict__ in, const float* __restrict__ w,
        const float* __restrict__ sc, const float* __restrict__ bi,
        float* __restrict__ outbuf) {
    __shared__ u64 ws[K * 32];       // [c][o]
    int t = threadIdx.x;
    for (int i = t; i < K * 32; i += 256) {
        int c = i >> 5, o = i & 31;
        float v = w[o * K + c];
        ws[i] = pk2(v, v);
    }
    __syncthreads();

    int warp = t >> 5, lane = t & 31;
    int og = warp & 1, pset = warp >> 1;
    int pair = pset * 32 + lane;                 // 0..127
    int pos0 = blockIdx.x * 256 + pair * 2;
    int b = pos0 >> 15, s = pos0 & (S - 1);

    u64 acc[16];
#pragma unroll
    for (int o = 0; o < 16; o++) acc[o] = 0ull;

    const float* ib = in + b * K * S + s;
#pragma unroll 4
    for (int c = 0; c < K; c++) {
        u64 xq = *(const u64*)(ib + c * S);
        const u64* wr = ws + c * 32 + og * 16;
#pragma unroll
        for (int o = 0; o < 16; o++) fma2(acc[o], wr[o], xq);
    }
#pragma unroll
    for (int o = 0; o < 16; o++) {
        int oo = og * 16 + o;
        float scv = __ldg(sc + oo), biv = __ldg(bi + oo);
        float a, bq; upk2(acc[o], a, bq);
        u64 r = pk2(fmaxf(a * scv + biv, 0.f), fmaxf(bq * scv + biv, 0.f));
        *(u64*)(outbuf + (b * CM + oo) * S + s) = r;
    }
}

__global__ void __launch_bounds__(256) k1_cv1(
        const float* __restrict__ x, const float* __restrict__ w1,
        const float* __restrict__ s1, const float* __restrict__ b1) {
    cv_body<64>(x, w1, s1, b1, g_a1);          // globals resolved device-side
}

__global__ void __launch_bounds__(256) k3a_cv3(
        const float* __restrict__ w3, const float* __restrict__ s3,
        const float* __restrict__ b3) {
    cv_body<32>(g_a2, w3, s3, b3, g_a1);
}

// ---------------- k2: depthwise 5x5x5 (zero pad) + BN, f32x2 ----------------
__global__ void __launch_bounds__(128) k2_dw5(
        const float* __restrict__ w2, const float* __restrict__ s2,
        const float* __restrict__ b2) {
    int blk = blockIdx.x;            // (b*32+c)*32+d
    int d = blk & 31;
    int c = (blk >> 5) & 31;
    int b = blk >> 10;
    int t = threadIdx.x;
    int wq = t & 3, h = t >> 2;
    int w0 = wq * 8;

    const float* src = g_a1 + (b * CM + c) * S;
    const float* wc  = w2 + c * 125;
    const float4 zero4 = make_float4(0.f, 0.f, 0.f, 0.f);

    u64 acc[4];
#pragma unroll
    for (int m = 0; m < 4; m++) acc[m] = 0ull;

    for (int dd = 0; dd < 5; dd++) {
        int zd = d + dd - 2;
        if ((unsigned)zd >= 32u) continue;
        for (int dh = 0; dh < 5; dh++) {
            int zh = h + dh - 2;
            if ((unsigned)zh >= 32u) continue;
            const float* row = src + (zd * 32 + zh) * 32;
            float4 f0 = (wq > 0) ? *(const float4*)(row + w0 - 4) : zero4;
            float4 f1 = *(const float4*)(row + w0);
            float4 f2 = *(const float4*)(row + w0 + 4);
            float4 f3 = (wq < 3) ? *(const float4*)(row + w0 + 8) : zero4;
            u64 A0 = pk2(f0.z, f0.w), A1 = pk2(f1.x, f1.y), A2 = pk2(f1.z, f1.w);
            u64 A3 = pk2(f2.x, f2.y), A4 = pk2(f2.z, f2.w), A5 = pk2(f3.x, f3.y);
            u64 M0 = pk2(f0.w, f1.x), M1 = pk2(f1.y, f1.z), M2 = pk2(f1.w, f2.x);
            u64 M3 = pk2(f2.y, f2.z), M4 = pk2(f2.w, f3.x);
            const float* wr = wc + (dd * 5 + dh) * 5;
            u64 T0 = pk2(wr[0], wr[0]), T1 = pk2(wr[1], wr[1]), T2 = pk2(wr[2], wr[2]);
            u64 T3 = pk2(wr[3], wr[3]), T4 = pk2(wr[4], wr[4]);
            fma2(acc[0], T0, A0); fma2(acc[0], T1, M0); fma2(acc[0], T2, A1);
            fma2(acc[0], T3, M1); fma2(acc[0], T4, A2);
            fma2(acc[1], T0, A1); fma2(acc[1], T1, M1); fma2(acc[1], T2, A2);
            fma2(acc[1], T3, M2); fma2(acc[1], T4, A3);
            fma2(acc[2], T0, A2); fma2(acc[2], T1, M2); fma2(acc[2], T2, A3);
            fma2(acc[2], T3, M3); fma2(acc[2], T4, A4);
            fma2(acc[3], T0, A3); fma2(acc[3], T1, M3); fma2(acc[3], T2, A4);
            fma2(acc[3], T3, M4); fma2(acc[3], T4, A5);
        }
    }
    float scv = s2[c], biv = b2[c];
    float* dst = g_a2 + (b * CM + c) * S + (d * 32 + h) * 32 + w0;
#pragma unroll
    for (int m = 0; m < 4; m++) {
        float a, bb; upk2(acc[m], a, bb);
        *(u64*)(dst + 2 * m) = pk2(a * scv + biv, bb * scv + biv);
    }
}

// ---------------- k3b: cv4 (32->216) + b4 + GN partial sums ----------------
// block 864 = 27 warps (8 outs each); weights [c][kk] (kk contiguous per warp).
__global__ void __launch_bounds__(864, 1) k3b_cv4(
        const float* __restrict__ w4, const float* __restrict__ b4) {
    extern __shared__ u64 sm[];
    u64* wp = sm;              // [c][216] = 6912
    u64* ap = sm + 6912;       // 32 c x 32 pairs = 1024
    __shared__ float redsum[NG], redsq[NG];
    int t = threadIdx.x;
    for (int i = t; i < KCH * CM; i += 864) {
        int c = i / KCH, kk = i - c * KCH;
        float v = w4[kk * CM + c];
        wp[i] = pk2(v, v);
    }
    if (t < NG) { redsum[t] = 0.f; redsq[t] = 0.f; }

    int pos0 = blockIdx.x * 64;
    int b = pos0 >> 15, s = pos0 & (S - 1);
    for (int i = t; i < 1024; i += 864) {
        int c = i >> 5, j = i & 31;
        ap[i] = *(const u64*)(g_a1 + (b * CM + c) * S + s + 2 * j);
    }
    __syncthreads();

    int og = t >> 5, lane = t & 31;   // og = 0..26
    u64 acc[8];
#pragma unroll
    for (int o = 0; o < 8; o++) { float bv = __ldg(b4 + og * 8 + o); acc[o] = pk2(bv, bv); }

#pragma unroll 4
    for (int c = 0; c < CM; c++) {
        u64 aq = ap[c * 32 + lane];
        const u64* wr = wp + c * KCH + og * 8;
#pragma unroll
        for (int o = 0; o < 8; o++) fma2(acc[o], wr[o], aq);
    }

    int kk0 = og * 8;
    int g0 = kk0 / 27;
    int brk = (g0 + 1) * 27 - kk0;       // o < brk -> group g0, else g0+1
    float su0 = 0.f, sq0 = 0.f, su1 = 0.f, sq1 = 0.f;
#pragma unroll
    for (int o = 0; o < 8; o++) {
        int kk = kk0 + o;
        *(u64*)(g_wk + (b * KCH + kk) * S + s + 2 * lane) = acc[o];
        float a, bv; upk2(acc[o], a, bv);
        float ss = a + bv, qq = a * a + bv * bv;
        if (o < brk) { su0 += ss; sq0 += qq; } else { su1 += ss; sq1 += qq; }
    }
#pragma unroll
    for (int off = 16; off; off >>= 1) {
        su0 += __shfl_down_sync(0xffffffffu, su0, off);
        sq0 += __shfl_down_sync(0xffffffffu, sq0, off);
        su1 += __shfl_down_sync(0xffffffffu, su1, off);
        sq1 += __shfl_down_sync(0xffffffffu, sq1, off);
    }
    if (lane == 0) {
        atomicAdd(&redsum[g0], su0); atomicAdd(&redsq[g0], sq0);
        if (brk < 8) { atomicAdd(&redsum[g0 + 1], su1); atomicAdd(&redsq[g0 + 1], sq1); }
    }
    __syncthreads();
    if (t < NG) {
        atomicAdd(&g_sum[b * NG + t], redsum[t]);
        atomicAdd(&g_sq [b * NG + t], redsq[t]);
    }
}

// ---------------- k4: finalize GN stats, then reset accumulators ----------------
__global__ void k4_stats() {
    int i = threadIdx.x;
    if (i < NB * NG) {
        float n  = 27.f * (float)S;
        float mu = g_sum[i] / n;
        float var = g_sq[i] / n - mu * mu;
        g_mu[i] = mu;
        g_rstd[i] = rsqrtf(var + 1e-5f);
        g_sum[i] = 0.f;          // restore zero-invariant for next call
        g_sq[i]  = 0.f;
    }
}

// ---------------- k5: GN affine + SKA (circular) + BN + residual -> y ------
__global__ void k5_ska(const float* __restrict__ x,
                       const float* __restrict__ gn_g, const float* __restrict__ gn_b,
                       const float* __restrict__ bn_s, const float* __restrict__ bn_b) {
    int gid = blockIdx.x * blockDim.x + threadIdx.x;   // 0 .. 131071
    int wq = gid & 7;
    int h  = (gid >> 3) & 31;
    int d  = (gid >> 8) & 31;
    int g  = (gid >> 13) & 7;
    int b  = gid >> 16;
    int w0 = wq * 4;
    int sbase = (d * 32 + h) * 32 + w0;

    float mu = g_mu[b * NG + g], rs = g_rstd[b * NG + g];

    u64 kvL[27], kvH[27];
    const float* wsrc = g_wk + (b * KCH + g * 27) * S + sbase;
#pragma unroll
    for (int k = 0; k < 27; k++) {
        float4 q = *(const float4*)(wsrc + k * S);
        int ch = g * 27 + k;
        float gg = __ldg(gn_g + ch) * rs;
        float bb = __ldg(gn_b + ch) - mu * gg;
        kvL[k] = pk2(q.x * gg + bb, q.y * gg + bb);
        kvH[k] = pk2(q.z * gg + bb, q.w * gg + bb);
    }

    const float* xg = x + (b * CIN + g * CPG) * S;
    float* yg = g_y + (b * CIN + g * CPG) * S;

    for (int c = 0; c < CPG; c++) {
        const float* xc = xg + c * S;
        u64 aL = 0ull, aH = 0ull;
        int k = 0;
#pragma unroll
        for (int di = -1; di <= 1; di++) {
            int zd = (d + di) & 31;
#pragma unroll
            for (int hi = -1; hi <= 1; hi++) {
                int zh = (h + hi) & 31;
                const float* row = xc + (zd * 32 + zh) * 32;
                float4 mid = *(const float4*)(row + w0);
                float v0 = row[(w0 - 1) & 31];
                float v5 = row[(w0 + 4) & 31];
                u64 p01 = pk2(v0,    mid.x);
                u64 p12 = pk2(mid.x, mid.y);
                u64 p23 = pk2(mid.y, mid.z);
                u64 p34 = pk2(mid.z, mid.w);
                u64 p45 = pk2(mid.w, v5);
                fma2(aL, kvL[k + 0], p01); fma2(aH, kvH[k + 0], p23);
                fma2(aL, kvL[k + 1], p12); fma2(aH, kvH[k + 1], p34);
                fma2(aL, kvL[k + 2], p23); fma2(aH, kvH[k + 2], p45);
                k += 3;
            }
        }
        float a0, a1v, a2v, a3v;
        upk2(aL, a0, a1v); upk2(aH, a2v, a3v);
        int ch = g * CPG + c;
        float bs_ = __ldg(bn_s + ch), bb_ = __ldg(bn_b + ch);
        float4 xq = *(const float4*)(xc + sbase);
        float4 r;
        r.x = a0  * bs_ + bb_ + xq.x;
        r.y = a1v * bs_ + bb_ + xq.y;
        r.z = a2v * bs_ + bb_ + xq.z;
        r.w = a3v * bs_ + bb_ + xq.w;
        *(float4*)(yg + c * S + sbase) = r;
    }
}

// ---------------- k6a: pw1 (64->128) + BN + ReLU ----------------
// block 256 = 8 warps, warp = og (16 outs); thread = 4 pos (pairs lane, lane+32).
// Weights [c][o] in 64KB smem; y via L1-cached LDG.
__global__ void __launch_bounds__(256) k6a_pw1(
        const float* __restrict__ w, const float* __restrict__ sc,
        const float* __restrict__ bi) {
    extern __shared__ u64 sm[];
    u64* wp = sm;              // [c][128] = 8192 u64 = 64KB
    int t = threadIdx.x;
    for (int i = t; i < 8192; i += 256) {
        int c = i >> 7, o = i & 127;
        float v = w[o * 64 + c];
        wp[i] = pk2(v, v);
    }
    __syncthreads();

    int og = t >> 5, lane = t & 31;     // og 0..7
    int pos0 = blockIdx.x * 128;        // grid 512
    int b = pos0 >> 15, s = pos0 & (S - 1);

    u64 accA[16], accB[16];
#pragma unroll
    for (int o = 0; o < 16; o++) { accA[o] = 0ull; accB[o] = 0ull; }

    const float* yb = g_y + b * CIN * S + s;
#pragma unroll 2
    for (int c = 0; c < CIN; c++) {
        const float* yr = yb + c * S;
        u64 yqA = *(const u64*)(yr + 2 * lane);
        u64 yqB = *(const u64*)(yr + 64 + 2 * lane);
        const u64* wr = wp + c * 128 + og * 16;
#pragma unroll
        for (int o = 0; o < 16; o++) {
            fma2(accA[o], wr[o], yqA);
            fma2(accB[o], wr[o], yqB);
        }
    }
#pragma unroll
    for (int o = 0; o < 16; o++) {
        int oo = og * 16 + o;
        float scv = __ldg(sc + oo), biv = __ldg(bi + oo);
        float a, bq;
        float* hb = g_h + (b * 128 + oo) * S + s;
        upk2(accA[o], a, bq);
        *(u64*)(hb + 2 * lane) = pk2(fmaxf(a * scv + biv, 0.f), fmaxf(bq * scv + biv, 0.f));
        upk2(accB[o], a, bq);
        *(u64*)(hb + 64 + 2 * lane) = pk2(fmaxf(a * scv + biv, 0.f), fmaxf(bq * scv + biv, 0.f));
    }
}

// ---------------- k6b: pw2 (128->64) + BN + add y -> out ----------------
// block 256 = 8 warps: og = warp&3 (16 outs), pset = warp>>2; 256 pos/block.
__global__ void __launch_bounds__(256) k6b_pw2(
        const float* __restrict__ w, const float* __restrict__ sc,
        const float* __restrict__ bi, float* __restrict__ out) {
    extern __shared__ u64 sm[];
    u64* wp = sm;              // [c][64] = 8192 u64 = 64KB
    int t = threadIdx.x;
    for (int i = t; i < 8192; i += 256) {
        int c = i >> 6, o = i & 63;
        float v = w[o * 128 + c];
        wp[i] = pk2(v, v);
    }
    __syncthreads();

    int warp = t >> 5, lane = t & 31;
    int og = warp & 3, pset = warp >> 2;      // og 0..3, pset 0..1
    int p0 = pset * 64 + lane;                // pairs p0, p0+32
    int pos0 = blockIdx.x * 256;              // grid 256
    int b = pos0 >> 15, s = pos0 & (S - 1);

    u64 accA[16], accB[16];
#pragma unroll
    for (int o = 0; o < 16; o++) { accA[o] = 0ull; accB[o] = 0ull; }

    const float* hb = g_h + b * 128 * S + s;
#pragma unroll 2
    for (int c = 0; c < 128; c++) {
        const float* hr = hb + c * S;
        u64 hqA = *(const u64*)(hr + 2 * p0);
        u64 hqB = *(const u64*)(hr + 2 * p0 + 64);
        const u64* wr = wp + c * 64 + og * 16;
#pragma unroll
        for (int o = 0; o < 16; o++) {
            fma2(accA[o], wr[o], hqA);
            fma2(accB[o], wr[o], hqB);
        }
    }
#pragma unroll
    for (int o = 0; o < 16; o++) {
        int oo = og * 16 + o;
        float scv = __ldg(sc + oo), biv = __ldg(bi + oo);
        const float* yb = g_y + (b * CIN + oo) * S + s;
        float* ob = out + (b * CIN + oo) * S + s;
        float a, bq, y0, y1;
        upk2(accA[o], a, bq);
        upk2(*(const u64*)(yb + 2 * p0), y0, y1);
        *(u64*)(ob + 2 * p0) = pk2(y0 + a * scv + biv, y1 + bq * scv + biv);
        upk2(accB[o], a, bq);
        upk2(*(const u64*)(yb + 2 * p0 + 64), y0, y1);
        *(u64*)(ob + 2 * p0 + 64) = pk2(y0 + a * scv + biv, y1 + bq * scv + biv);
    }
}

// ---------------- launcher ----------------
extern "C" void kernel_launch(void* const* d_in, const int* in_sizes, int n_in,
                              void* d_out, int out_size) {
    const float* x     = (const float*)d_in[0];
    const float* w1    = (const float*)d_in[1];
    const float* s1    = (const float*)d_in[2];
    const float* b1    = (const float*)d_in[3];
    const float* w2    = (const float*)d_in[4];
    const float* s2    = (const float*)d_in[5];
    const float* b2    = (const float*)d_in[6];
    const float* w3    = (const float*)d_in[7];
    const float* s3    = (const float*)d_in[8];
    const float* b3    = (const float*)d_in[9];
    const float* w4    = (const float*)d_in[10];
    const float* b4    = (const float*)d_in[11];
    const float* gn_g  = (const float*)d_in[12];
    const float* gn_b  = (const float*)d_in[13];
    const float* bn_s  = (const float*)d_in[14];
    const float* bn_b  = (const float*)d_in[15];
    const float* pw1_w = (const float*)d_in[16];
    const float* pw1_s = (const float*)d_in[17];
    const float* pw1_b = (const float*)d_in[18];
    const float* pw2_w = (const float*)d_in[19];
    const float* pw2_s = (const float*)d_in[20];
    const float* pw2_b = (const float*)d_in[21];
    float* out = (float*)d_out;

    const int smem_k3b = (KCH * CM + 1024) * 8;      // 63.5 KB
    const int smem_k6  = 8192 * 8;                   // 64 KB
    cudaFuncSetAttribute(k3b_cv4, cudaFuncAttributeMaxDynamicSharedMemorySize, smem_k3b);
    cudaFuncSetAttribute(k6a_pw1, cudaFuncAttributeMaxDynamicSharedMemorySize, smem_k6);
    cudaFuncSetAttribute(k6b_pw2, cudaFuncAttributeMaxDynamicSharedMemorySize, smem_k6);

    k1_cv1  <<<256, 256>>>(x, w1, s1, b1);           // launch 0: 256 pos/block
    k2_dw5  <<<2048, 128>>>(w2, s2, b2);             // launch 1
    k3a_cv3 <<<256, 256>>>(w3, s3, b3);              // launch 2
    k3b_cv4 <<<1024, 864, smem_k3b>>>(w4, b4);       // launch 3  <- profiled slot
    k4_stats<<<1, 32>>>();                           // launch 4 (also resets sums)
    k5_ska  <<<1024, 128>>>(x, gn_g, gn_b, bn_s, bn_b); // launch 5
    k6a_pw1 <<<512, 256, smem_k6>>>(pw1_w, pw1_s, pw1_b);       // launch 6
    k6b_pw2 <<<256, 256, smem_k6>>>(pw2_w, pw2_s, pw2_b, out);  // launch 7
}

// round 9
// speedup vs baseline: 1.1767x; 1.0457x over previous
#include <cuda_runtime.h>

#define S   32768          // 32*32*32 spatial
#define NB  2              // batch
#define CIN 64
#define CM  32             // mid channels
#define KCH 216            // dynamic kernel channels
#define NG  8              // groups
#define CPG 8              // channels per group (64/8)

typedef unsigned long long u64;

// ---------------- f32x2 helpers ----------------
__device__ __forceinline__ u64 pk2(float a, float b) {
    u64 r; asm("mov.b64 %0,{%1,%2};" : "=l"(r) : "f"(a), "f"(b)); return r;
}
__device__ __forceinline__ void upk2(u64 v, float& a, float& b) {
    asm("mov.b64 {%0,%1},%2;" : "=f"(a), "=f"(b) : "l"(v));
}
__device__ __forceinline__ void fma2(u64& d, u64 a, u64 b) {
    asm("fma.rn.f32x2 %0,%1,%2,%0;" : "+l"(d) : "l"(a), "l"(b));
}

// ---------------- scratch (device globals; allocation-free) ----------------
__device__ float g_a1[NB * CM  * S];   // cv1 out; later reused for cv3 out (a3)
__device__ float g_a2[NB * CM  * S];   // after dw5+bn
__device__ float g_wk[NB * KCH * S];   // cv4 output (pre-GN)
__device__ float g_y [NB * CIN * S];   // after SKA + bn + residual
__device__ float g_h [NB * 128 * S];   // FFN hidden
__device__ float g_sum[NB * NG];       // zero-init; k4 re-zeros after use
__device__ float g_sq [NB * NG];
__device__ float g_mu [NB * NG];
__device__ float g_rstd[NB * NG];

// ---------------- cv body: K->32 1x1 conv + BN + ReLU ----------------
// block 256 = 8 warps: og = warp&1 (16 outs), pset = warp>>1 (4 sets).
// thread = 2 pair-slots (4 positions); weights [c][o] in smem (LDS.128).
template<int K>
__device__ __forceinline__ void cv_body(
        const float* __restrict__ in, const float* __restrict__ w,
        const float* __restrict__ sc, const float* __restrict__ bi,
        float* __restrict__ outbuf) {
    __shared__ u64 ws[K * 32];       // [c][o]
    int t = threadIdx.x;
    for (int i = t; i < K * 32; i += 256) {
        int c = i >> 5, o = i & 31;
        float v = w[o * K + c];
        ws[i] = pk2(v, v);
    }
    __syncthreads();

    int warp = t >> 5, lane = t & 31;
    int og = warp & 1, pset = warp >> 1;
    int pr = pset * 32 + lane;                  // pair-slot 0..127
    int pos0 = blockIdx.x * 512;                // 512 positions per block
    int b = pos0 >> 15, s = pos0 & (S - 1);
    int sA = s + 2 * pr;                        // first pair
    int sB = sA + 256;                          // second pair (pr+128)

    u64 accA[16], accB[16];
#pragma unroll
    for (int o = 0; o < 16; o++) { accA[o] = 0ull; accB[o] = 0ull; }

    const float* ib = in + b * K * S;
#pragma unroll 2
    for (int c = 0; c < K; c++) {
        u64 xqA = *(const u64*)(ib + c * S + sA);
        u64 xqB = *(const u64*)(ib + c * S + sB);
        const u64* wr = ws + c * 32 + og * 16;
#pragma unroll
        for (int o = 0; o < 16; o++) {
            u64 wv = wr[o];
            fma2(accA[o], wv, xqA);
            fma2(accB[o], wv, xqB);
        }
    }
#pragma unroll
    for (int o = 0; o < 16; o++) {
        int oo = og * 16 + o;
        float scv = __ldg(sc + oo), biv = __ldg(bi + oo);
        float a, bq;
        float* ob = outbuf + (b * CM + oo) * S;
        upk2(accA[o], a, bq);
        *(u64*)(ob + sA) = pk2(fmaxf(a * scv + biv, 0.f), fmaxf(bq * scv + biv, 0.f));
        upk2(accB[o], a, bq);
        *(u64*)(ob + sB) = pk2(fmaxf(a * scv + biv, 0.f), fmaxf(bq * scv + biv, 0.f));
    }
}

__global__ void __launch_bounds__(256) k1_cv1(
        const float* __restrict__ x, const float* __restrict__ w1,
        const float* __restrict__ s1, const float* __restrict__ b1) {
    cv_body<64>(x, w1, s1, b1, g_a1);          // globals resolved device-side
}

__global__ void __launch_bounds__(256) k3a_cv3(
        const float* __restrict__ w3, const float* __restrict__ s3,
        const float* __restrict__ b3) {
    cv_body<32>(g_a2, w3, s3, b3, g_a1);
}

// ---------------- k2: depthwise 5x5x5 (zero pad) + BN, f32x2 ----------------
__global__ void __launch_bounds__(128) k2_dw5(
        const float* __restrict__ w2, const float* __restrict__ s2,
        const float* __restrict__ b2) {
    int blk = blockIdx.x;            // (b*32+c)*32+d
    int d = blk & 31;
    int c = (blk >> 5) & 31;
    int b = blk >> 10;
    int t = threadIdx.x;
    int wq = t & 3, h = t >> 2;
    int w0 = wq * 8;

    const float* src = g_a1 + (b * CM + c) * S;
    const float* wc  = w2 + c * 125;
    const float4 zero4 = make_float4(0.f, 0.f, 0.f, 0.f);

    u64 acc[4];
#pragma unroll
    for (int m = 0; m < 4; m++) acc[m] = 0ull;

    for (int dd = 0; dd < 5; dd++) {
        int zd = d + dd - 2;
        if ((unsigned)zd >= 32u) continue;
        for (int dh = 0; dh < 5; dh++) {
            int zh = h + dh - 2;
            if ((unsigned)zh >= 32u) continue;
            const float* row = src + (zd * 32 + zh) * 32;
            float4 f0 = (wq > 0) ? *(const float4*)(row + w0 - 4) : zero4;
            float4 f1 = *(const float4*)(row + w0);
            float4 f2 = *(const float4*)(row + w0 + 4);
            float4 f3 = (wq < 3) ? *(const float4*)(row + w0 + 8) : zero4;
            u64 A0 = pk2(f0.z, f0.w), A1 = pk2(f1.x, f1.y), A2 = pk2(f1.z, f1.w);
            u64 A3 = pk2(f2.x, f2.y), A4 = pk2(f2.z, f2.w), A5 = pk2(f3.x, f3.y);
            u64 M0 = pk2(f0.w, f1.x), M1 = pk2(f1.y, f1.z), M2 = pk2(f1.w, f2.x);
            u64 M3 = pk2(f2.y, f2.z), M4 = pk2(f2.w, f3.x);
            const float* wr = wc + (dd * 5 + dh) * 5;
            u64 T0 = pk2(wr[0], wr[0]), T1 = pk2(wr[1], wr[1]), T2 = pk2(wr[2], wr[2]);
            u64 T3 = pk2(wr[3], wr[3]), T4 = pk2(wr[4], wr[4]);
            fma2(acc[0], T0, A0); fma2(acc[0], T1, M0); fma2(acc[0], T2, A1);
            fma2(acc[0], T3, M1); fma2(acc[0], T4, A2);
            fma2(acc[1], T0, A1); fma2(acc[1], T1, M1); fma2(acc[1], T2, A2);
            fma2(acc[1], T3, M2); fma2(acc[1], T4, A3);
            fma2(acc[2], T0, A2); fma2(acc[2], T1, M2); fma2(acc[2], T2, A3);
            fma2(acc[2], T3, M3); fma2(acc[2], T4, A4);
            fma2(acc[3], T0, A3); fma2(acc[3], T1, M3); fma2(acc[3], T2, A4);
            fma2(acc[3], T3, M4); fma2(acc[3], T4, A5);
        }
    }
    float scv = s2[c], biv = b2[c];
    float* dst = g_a2 + (b * CM + c) * S + (d * 32 + h) * 32 + w0;
#pragma unroll
    for (int m = 0; m < 4; m++) {
        float a, bb; upk2(acc[m], a, bb);
        *(u64*)(dst + 2 * m) = pk2(a * scv + biv, bb * scv + biv);
    }
}

// ---------------- k3b: cv4 (32->216) + b4 + GN partial sums ----------------
// block 864 = 27 warps (8 outs each); thread = 2 pair-slots (128 pos/block).
// Weights [c][kk] in smem (uniform LDS.128); activations staged in smem.
__global__ void __launch_bounds__(864, 1) k3b_cv4(
        const float* __restrict__ w4, const float* __restrict__ b4) {
    extern __shared__ u64 sm[];
    u64* wp = sm;              // [c][216] = 6912
    u64* ap = sm + 6912;       // 32 c x 64 pairs = 2048
    __shared__ float redsum[NG], redsq[NG];
    int t = threadIdx.x;
    for (int i = t; i < KCH * CM; i += 864) {
        int c = i / KCH, kk = i - c * KCH;
        float v = w4[kk * CM + c];
        wp[i] = pk2(v, v);
    }
    if (t < NG) { redsum[t] = 0.f; redsq[t] = 0.f; }

    int pos0 = blockIdx.x * 128;               // grid 512
    int b = pos0 >> 15, s = pos0 & (S - 1);
    for (int i = t; i < 2048; i += 864) {
        int c = i >> 6, j = i & 63;
        ap[i] = *(const u64*)(g_a1 + (b * CM + c) * S + s + 2 * j);
    }
    __syncthreads();

    int og = t >> 5, lane = t & 31;   // og = 0..26
    u64 accA[8], accB[8];
#pragma unroll
    for (int o = 0; o < 8; o++) {
        float bv = __ldg(b4 + og * 8 + o);
        accA[o] = pk2(bv, bv); accB[o] = pk2(bv, bv);
    }

#pragma unroll 2
    for (int c = 0; c < CM; c++) {
        u64 aqA = ap[c * 64 + lane];
        u64 aqB = ap[c * 64 + 32 + lane];
        const u64* wr = wp + c * KCH + og * 8;
#pragma unroll
        for (int o = 0; o < 8; o++) {
            u64 wv = wr[o];
            fma2(accA[o], wv, aqA);
            fma2(accB[o], wv, aqB);
        }
    }

    int kk0 = og * 8;
    int g0 = kk0 / 27;
    int brk = (g0 + 1) * 27 - kk0;       // o < brk -> group g0, else g0+1
    float su0 = 0.f, sq0 = 0.f, su1 = 0.f, sq1 = 0.f;
#pragma unroll
    for (int o = 0; o < 8; o++) {
        int kk = kk0 + o;
        float* dst = g_wk + (b * KCH + kk) * S + s;
        *(u64*)(dst + 2 * lane) = accA[o];
        *(u64*)(dst + 64 + 2 * lane) = accB[o];
        float a0, b0, a1, b1;
        upk2(accA[o], a0, b0); upk2(accB[o], a1, b1);
        float ss = a0 + b0 + a1 + b1;
        float qq = a0 * a0 + b0 * b0 + a1 * a1 + b1 * b1;
        if (o < brk) { su0 += ss; sq0 += qq; } else { su1 += ss; sq1 += qq; }
    }
#pragma unroll
    for (int off = 16; off; off >>= 1) {
        su0 += __shfl_down_sync(0xffffffffu, su0, off);
        sq0 += __shfl_down_sync(0xffffffffu, sq0, off);
        su1 += __shfl_down_sync(0xffffffffu, su1, off);
        sq1 += __shfl_down_sync(0xffffffffu, sq1, off);
    }
    if (lane == 0) {
        atomicAdd(&redsum[g0], su0); atomicAdd(&redsq[g0], sq0);
        if (brk < 8) { atomicAdd(&redsum[g0 + 1], su1); atomicAdd(&redsq[g0 + 1], sq1); }
    }
    __syncthreads();
    if (t < NG) {
        atomicAdd(&g_sum[b * NG + t], redsum[t]);
        atomicAdd(&g_sq [b * NG + t], redsq[t]);
    }
}

// ---------------- k4: finalize GN stats, then reset accumulators ----------------
__global__ void k4_stats() {
    int i = threadIdx.x;
    if (i < NB * NG) {
        float n  = 27.f * (float)S;
        float mu = g_sum[i] / n;
        float var = g_sq[i] / n - mu * mu;
        g_mu[i] = mu;
        g_rstd[i] = rsqrtf(var + 1e-5f);
        g_sum[i] = 0.f;          // restore zero-invariant for next call
        g_sq[i]  = 0.f;
    }
}

// ---------------- k5: GN affine + SKA (circular) + BN + residual -> y ------
__global__ void k5_ska(const float* __restrict__ x,
                       const float* __restrict__ gn_g, const float* __restrict__ gn_b,
                       const float* __restrict__ bn_s, const float* __restrict__ bn_b) {
    int gid = blockIdx.x * blockDim.x + threadIdx.x;   // 0 .. 131071
    int wq = gid & 7;
    int h  = (gid >> 3) & 31;
    int d  = (gid >> 8) & 31;
    int g  = (gid >> 13) & 7;
    int b  = gid >> 16;
    int w0 = wq * 4;
    int sbase = (d * 32 + h) * 32 + w0;

    float mu = g_mu[b * NG + g], rs = g_rstd[b * NG + g];

    u64 kvL[27], kvH[27];
    const float* wsrc = g_wk + (b * KCH + g * 27) * S + sbase;
#pragma unroll
    for (int k = 0; k < 27; k++) {
        float4 q = *(const float4*)(wsrc + k * S);
        int ch = g * 27 + k;
        float gg = __ldg(gn_g + ch) * rs;
        float bb = __ldg(gn_b + ch) - mu * gg;
        kvL[k] = pk2(q.x * gg + bb, q.y * gg + bb);
        kvH[k] = pk2(q.z * gg + bb, q.w * gg + bb);
    }

    const float* xg = x + (b * CIN + g * CPG) * S;
    float* yg = g_y + (b * CIN + g * CPG) * S;

    for (int c = 0; c < CPG; c++) {
        const float* xc = xg + c * S;
        u64 aL = 0ull, aH = 0ull;
        int k = 0;
#pragma unroll
        for (int di = -1; di <= 1; di++) {
            int zd = (d + di) & 31;
#pragma unroll
            for (int hi = -1; hi <= 1; hi++) {
                int zh = (h + hi) & 31;
                const float* row = xc + (zd * 32 + zh) * 32;
                float4 mid = *(const float4*)(row + w0);
                float v0 = row[(w0 - 1) & 31];
                float v5 = row[(w0 + 4) & 31];
                u64 p01 = pk2(v0,    mid.x);
                u64 p12 = pk2(mid.x, mid.y);
                u64 p23 = pk2(mid.y, mid.z);
                u64 p34 = pk2(mid.z, mid.w);
                u64 p45 = pk2(mid.w, v5);
                fma2(aL, kvL[k + 0], p01); fma2(aH, kvH[k + 0], p23);
                fma2(aL, kvL[k + 1], p12); fma2(aH, kvH[k + 1], p34);
                fma2(aL, kvL[k + 2], p23); fma2(aH, kvH[k + 2], p45);
                k += 3;
            }
        }
        float a0, a1v, a2v, a3v;
        upk2(aL, a0, a1v); upk2(aH, a2v, a3v);
        int ch = g * CPG + c;
        float bs_ = __ldg(bn_s + ch), bb_ = __ldg(bn_b + ch);
        float4 xq = *(const float4*)(xc + sbase);
        float4 r;
        r.x = a0  * bs_ + bb_ + xq.x;
        r.y = a1v * bs_ + bb_ + xq.y;
        r.z = a2v * bs_ + bb_ + xq.z;
        r.w = a3v * bs_ + bb_ + xq.w;
        *(float4*)(yg + c * S + sbase) = r;
    }
}

// ---------------- k6a: pw1 (64->128) + BN + ReLU ----------------
// block 256 = 8 warps, warp = og (16 outs); thread = 2 pair-slots.
__global__ void __launch_bounds__(256) k6a_pw1(
        const float* __restrict__ w, const float* __restrict__ sc,
        const float* __restrict__ bi) {
    extern __shared__ u64 sm[];
    u64* wp = sm;              // [c][128] = 8192 u64 = 64KB
    int t = threadIdx.x;
    for (int i = t; i < 8192; i += 256) {
        int c = i >> 7, o = i & 127;
        float v = w[o * 64 + c];
        wp[i] = pk2(v, v);
    }
    __syncthreads();

    int og = t >> 5, lane = t & 31;     // og 0..7
    int pos0 = blockIdx.x * 128;        // grid 512
    int b = pos0 >> 15, s = pos0 & (S - 1);

    u64 accA[16], accB[16];
#pragma unroll
    for (int o = 0; o < 16; o++) { accA[o] = 0ull; accB[o] = 0ull; }

    const float* yb = g_y + b * CIN * S + s;
#pragma unroll 2
    for (int c = 0; c < CIN; c++) {
        const float* yr = yb + c * S;
        u64 yqA = *(const u64*)(yr + 2 * lane);
        u64 yqB = *(const u64*)(yr + 64 + 2 * lane);
        const u64* wr = wp + c * 128 + og * 16;
#pragma unroll
        for (int o = 0; o < 16; o++) {
            fma2(accA[o], wr[o], yqA);
            fma2(accB[o], wr[o], yqB);
        }
    }
#pragma unroll
    for (int o = 0; o < 16; o++) {
        int oo = og * 16 + o;
        float scv = __ldg(sc + oo), biv = __ldg(bi + oo);
        float a, bq;
        float* hb = g_h + (b * 128 + oo) * S + s;
        upk2(accA[o], a, bq);
        *(u64*)(hb + 2 * lane) = pk2(fmaxf(a * scv + biv, 0.f), fmaxf(bq * scv + biv, 0.f));
        upk2(accB[o], a, bq);
        *(u64*)(hb + 64 + 2 * lane) = pk2(fmaxf(a * scv + biv, 0.f), fmaxf(bq * scv + biv, 0.f));
    }
}

// ---------------- k6b: pw2 (128->64) + BN + add y -> out ----------------
// block 256 = 8 warps: og = warp&3 (16 outs), pset = warp>>2; 256 pos/block.
__global__ void __launch_bounds__(256) k6b_pw2(
        const float* __restrict__ w, const float* __restrict__ sc,
        const float* __restrict__ bi, float* __restrict__ out) {
    extern __shared__ u64 sm[];
    u64* wp = sm;              // [c][64] = 8192 u64 = 64KB
    int t = threadIdx.x;
    for (int i = t; i < 8192; i += 256) {
        int c = i >> 6, o = i & 63;
        float v = w[o * 128 + c];
        wp[i] = pk2(v, v);
    }
    __syncthreads();

    int warp = t >> 5, lane = t & 31;
    int og = warp & 3, pset = warp >> 2;      // og 0..3, pset 0..1
    int p0 = pset * 64 + lane;                // pairs p0, p0+32
    int pos0 = blockIdx.x * 256;              // grid 256
    int b = pos0 >> 15, s = pos0 & (S - 1);

    u64 accA[16], accB[16];
#pragma unroll
    for (int o = 0; o < 16; o++) { accA[o] = 0ull; accB[o] = 0ull; }

    const float* hb = g_h + b * 128 * S + s;
#pragma unroll 2
    for (int c = 0; c < 128; c++) {
        const float* hr = hb + c * S;
        u64 hqA = *(const u64*)(hr + 2 * p0);
        u64 hqB = *(const u64*)(hr + 2 * p0 + 64);
        const u64* wr = wp + c * 64 + og * 16;
#pragma unroll
        for (int o = 0; o < 16; o++) {
            fma2(accA[o], wr[o], hqA);
            fma2(accB[o], wr[o], hqB);
        }
    }
#pragma unroll
    for (int o = 0; o < 16; o++) {
        int oo = og * 16 + o;
        float scv = __ldg(sc + oo), biv = __ldg(bi + oo);
        const float* yb = g_y + (b * CIN + oo) * S + s;
        float* ob = out + (b * CIN + oo) * S + s;
        float a, bq, y0, y1;
        upk2(accA[o], a, bq);
        upk2(*(const u64*)(yb + 2 * p0), y0, y1);
        *(u64*)(ob + 2 * p0) = pk2(y0 + a * scv + biv, y1 + bq * scv + biv);
        upk2(accB[o], a, bq);
        upk2(*(const u64*)(yb + 2 * p0 + 64), y0, y1);
        *(u64*)(ob + 2 * p0 + 64) = pk2(y0 + a * scv + biv, y1 + bq * scv + biv);
    }
}

// ---------------- launcher ----------------
extern "C" void kernel_launch(void* const* d_in, const int* in_sizes, int n_in,
                              void* d_out, int out_size) {
    const float* x     = (const float*)d_in[0];
    const float* w1    = (const float*)d_in[1];
    const float* s1    = (const float*)d_in[2];
    const float* b1    = (const float*)d_in[3];
    const float* w2    = (const float*)d_in[4];
    const float* s2    = (const float*)d_in[5];
    const float* b2    = (const float*)d_in[6];
    const float* w3    = (const float*)d_in[7];
    const float* s3    = (const float*)d_in[8];
    const float* b3    = (const float*)d_in[9];
    const float* w4    = (const float*)d_in[10];
    const float* b4    = (const float*)d_in[11];
    const float* gn_g  = (const float*)d_in[12];
    const float* gn_b  = (const float*)d_in[13];
    const float* bn_s  = (const float*)d_in[14];
    const float* bn_b  = (const float*)d_in[15];
    const float* pw1_w = (const float*)d_in[16];
    const float* pw1_s = (const float*)d_in[17];
    const float* pw1_b = (const float*)d_in[18];
    const float* pw2_w = (const float*)d_in[19];
    const float* pw2_s = (const float*)d_in[20];
    const float* pw2_b = (const float*)d_in[21];
    float* out = (float*)d_out;

    const int smem_k3b = (KCH * CM + 2048) * 8;      // 70 KB
    const int smem_k6  = 8192 * 8;                   // 64 KB
    cudaFuncSetAttribute(k3b_cv4, cudaFuncAttributeMaxDynamicSharedMemorySize, smem_k3b);
    cudaFuncSetAttribute(k6a_pw1, cudaFuncAttributeMaxDynamicSharedMemorySize, smem_k6);
    cudaFuncSetAttribute(k6b_pw2, cudaFuncAttributeMaxDynamicSharedMemorySize, smem_k6);

    k1_cv1  <<<128, 256>>>(x, w1, s1, b1);           // launch 0: 512 pos/block
    k2_dw5  <<<2048, 128>>>(w2, s2, b2);             // launch 1
    k3a_cv3 <<<128, 256>>>(w3, s3, b3);              // launch 2
    k3b_cv4 <<<512, 864, smem_k3b>>>(w4, b4);        // launch 3  <- profiled slot
    k4_stats<<<1, 32>>>();                           // launch 4
    k5_ska  <<<1024, 128>>>(x, gn_g, gn_b, bn_s, bn_b); // launch 5
    k6a_pw1 <<<512, 256, smem_k6>>>(pw1_w, pw1_s, pw1_b);       // launch 6
    k6b_pw2 <<<256, 256, smem_k6>>>(pw2_w, pw2_s, pw2_b, out);  // launch 7
}

// round 10
// speedup vs baseline: 1.2000x; 1.0198x over previous
#include <cuda_runtime.h>

#define S   32768          // 32*32*32 spatial
#define NB  2              // batch
#define CIN 64
#define CM  32             // mid channels
#define KCH 216            // dynamic kernel channels
#define NG  8              // groups
#define CPG 8              // channels per group (64/8)

typedef unsigned long long u64;

// ---------------- f32x2 helpers ----------------
__device__ __forceinline__ u64 pk2(float a, float b) {
    u64 r; asm("mov.b64 %0,{%1,%2};" : "=l"(r) : "f"(a), "f"(b)); return r;
}
__device__ __forceinline__ void upk2(u64 v, float& a, float& b) {
    asm("mov.b64 {%0,%1},%2;" : "=f"(a), "=f"(b) : "l"(v));
}
__device__ __forceinline__ void fma2(u64& d, u64 a, u64 b) {
    asm("fma.rn.f32x2 %0,%1,%2,%0;" : "+l"(d) : "l"(a), "l"(b));
}

// ---------------- scratch (device globals; allocation-free) ----------------
__device__ float g_a1[NB * CM  * S];   // cv1 out; later reused for cv3 out (a3)
__device__ float g_a2[NB * CM  * S];   // after dw5+bn
__device__ float g_wk[NB * KCH * S];   // cv4 output (pre-GN)
__device__ float g_y [NB * CIN * S];   // after SKA + bn + residual
__device__ float g_h [NB * 128 * S];   // FFN hidden
__device__ float g_sum[NB * NG];       // zero-init; k4 re-zeros after use
__device__ float g_sq [NB * NG];
__device__ float g_mu [NB * NG];
__device__ float g_rstd[NB * NG];

// ---------------- cv body: K->32 1x1 conv + BN + ReLU ----------------
// block 256 = 8 warps: og = warp&1 (16 outs), pset = warp>>1 (4 sets).
// thread = 2 pair-slots (4 positions); weights [c][o] in smem (LDS.128).
template<int K>
__device__ __forceinline__ void cv_body(
        const float* __restrict__ in, const float* __restrict__ w,
        const float* __restrict__ sc, const float* __restrict__ bi,
        float* __restrict__ outbuf) {
    __shared__ u64 ws[K * 32];       // [c][o]
    int t = threadIdx.x;
    for (int i = t; i < K * 32; i += 256) {
        int c = i >> 5, o = i & 31;
        float v = w[o * K + c];
        ws[i] = pk2(v, v);
    }
    __syncthreads();

    int warp = t >> 5, lane = t & 31;
    int og = warp & 1, pset = warp >> 1;
    int pr = pset * 32 + lane;                  // pair-slot 0..127
    int pos0 = blockIdx.x * 512;                // 512 positions per block
    int b = pos0 >> 15, s = pos0 & (S - 1);
    int sA = s + 2 * pr;                        // first pair
    int sB = sA + 256;                          // second pair (pr+128)

    u64 accA[16], accB[16];
#pragma unroll
    for (int o = 0; o < 16; o++) { accA[o] = 0ull; accB[o] = 0ull; }

    const float* ib = in + b * K * S;
#pragma unroll 2
    for (int c = 0; c < K; c++) {
        u64 xqA = *(const u64*)(ib + c * S + sA);
        u64 xqB = *(const u64*)(ib + c * S + sB);
        const u64* wr = ws + c * 32 + og * 16;
#pragma unroll
        for (int o = 0; o < 16; o++) {
            u64 wv = wr[o];
            fma2(accA[o], wv, xqA);
            fma2(accB[o], wv, xqB);
        }
    }
#pragma unroll
    for (int o = 0; o < 16; o++) {
        int oo = og * 16 + o;
        float scv = __ldg(sc + oo), biv = __ldg(bi + oo);
        float a, bq;
        float* ob = outbuf + (b * CM + oo) * S;
        upk2(accA[o], a, bq);
        *(u64*)(ob + sA) = pk2(fmaxf(a * scv + biv, 0.f), fmaxf(bq * scv + biv, 0.f));
        upk2(accB[o], a, bq);
        *(u64*)(ob + sB) = pk2(fmaxf(a * scv + biv, 0.f), fmaxf(bq * scv + biv, 0.f));
    }
}

__global__ void __launch_bounds__(256) k1_cv1(
        const float* __restrict__ x, const float* __restrict__ w1,
        const float* __restrict__ s1, const float* __restrict__ b1) {
    cv_body<64>(x, w1, s1, b1, g_a1);          // globals resolved device-side
}

__global__ void __launch_bounds__(256) k3a_cv3(
        const float* __restrict__ w3, const float* __restrict__ s3,
        const float* __restrict__ b3) {
    cv_body<32>(g_a2, w3, s3, b3, g_a1);
}

// ---------------- k2: depthwise 5x5x5 (zero pad) + BN, f32x2 ----------------
__global__ void __launch_bounds__(128) k2_dw5(
        const float* __restrict__ w2, const float* __restrict__ s2,
        const float* __restrict__ b2) {
    int blk = blockIdx.x;            // (b*32+c)*32+d
    int d = blk & 31;
    int c = (blk >> 5) & 31;
    int b = blk >> 10;
    int t = threadIdx.x;
    int wq = t & 3, h = t >> 2;
    int w0 = wq * 8;

    const float* src = g_a1 + (b * CM + c) * S;
    const float* wc  = w2 + c * 125;
    const float4 zero4 = make_float4(0.f, 0.f, 0.f, 0.f);

    u64 acc[4];
#pragma unroll
    for (int m = 0; m < 4; m++) acc[m] = 0ull;

    for (int dd = 0; dd < 5; dd++) {
        int zd = d + dd - 2;
        if ((unsigned)zd >= 32u) continue;
        for (int dh = 0; dh < 5; dh++) {
            int zh = h + dh - 2;
            if ((unsigned)zh >= 32u) continue;
            const float* row = src + (zd * 32 + zh) * 32;
            float4 f0 = (wq > 0) ? *(const float4*)(row + w0 - 4) : zero4;
            float4 f1 = *(const float4*)(row + w0);
            float4 f2 = *(const float4*)(row + w0 + 4);
            float4 f3 = (wq < 3) ? *(const float4*)(row + w0 + 8) : zero4;
            u64 A0 = pk2(f0.z, f0.w), A1 = pk2(f1.x, f1.y), A2 = pk2(f1.z, f1.w);
            u64 A3 = pk2(f2.x, f2.y), A4 = pk2(f2.z, f2.w), A5 = pk2(f3.x, f3.y);
            u64 M0 = pk2(f0.w, f1.x), M1 = pk2(f1.y, f1.z), M2 = pk2(f1.w, f2.x);
            u64 M3 = pk2(f2.y, f2.z), M4 = pk2(f2.w, f3.x);
            const float* wr = wc + (dd * 5 + dh) * 5;
            u64 T0 = pk2(wr[0], wr[0]), T1 = pk2(wr[1], wr[1]), T2 = pk2(wr[2], wr[2]);
            u64 T3 = pk2(wr[3], wr[3]), T4 = pk2(wr[4], wr[4]);
            fma2(acc[0], T0, A0); fma2(acc[0], T1, M0); fma2(acc[0], T2, A1);
            fma2(acc[0], T3, M1); fma2(acc[0], T4, A2);
            fma2(acc[1], T0, A1); fma2(acc[1], T1, M1); fma2(acc[1], T2, A2);
            fma2(acc[1], T3, M2); fma2(acc[1], T4, A3);
            fma2(acc[2], T0, A2); fma2(acc[2], T1, M2); fma2(acc[2], T2, A3);
            fma2(acc[2], T3, M3); fma2(acc[2], T4, A4);
            fma2(acc[3], T0, A3); fma2(acc[3], T1, M3); fma2(acc[3], T2, A4);
            fma2(acc[3], T3, M4); fma2(acc[3], T4, A5);
        }
    }
    float scv = s2[c], biv = b2[c];
    float* dst = g_a2 + (b * CM + c) * S + (d * 32 + h) * 32 + w0;
#pragma unroll
    for (int m = 0; m < 4; m++) {
        float a, bb; upk2(acc[m], a, bb);
        *(u64*)(dst + 2 * m) = pk2(a * scv + biv, bb * scv + biv);
    }
}

// ---------------- k3b: cv4 (32->216) + b4 + GN partial sums ----------------
// block 864 = 27 warps (8 outs each); thread = 2 pair-slots (128 pos/block).
__global__ void __launch_bounds__(864, 1) k3b_cv4(
        const float* __restrict__ w4, const float* __restrict__ b4) {
    extern __shared__ u64 sm[];
    u64* wp = sm;              // [c][216] = 6912
    u64* ap = sm + 6912;       // 32 c x 64 pairs = 2048
    __shared__ float redsum[NG], redsq[NG];
    int t = threadIdx.x;
    for (int i = t; i < KCH * CM; i += 864) {
        int c = i / KCH, kk = i - c * KCH;
        float v = w4[kk * CM + c];
        wp[i] = pk2(v, v);
    }
    if (t < NG) { redsum[t] = 0.f; redsq[t] = 0.f; }

    int pos0 = blockIdx.x * 128;               // grid 512
    int b = pos0 >> 15, s = pos0 & (S - 1);
    for (int i = t; i < 2048; i += 864) {
        int c = i >> 6, j = i & 63;
        ap[i] = *(const u64*)(g_a1 + (b * CM + c) * S + s + 2 * j);
    }
    __syncthreads();

    int og = t >> 5, lane = t & 31;   // og = 0..26
    u64 accA[8], accB[8];
#pragma unroll
    for (int o = 0; o < 8; o++) {
        float bv = __ldg(b4 + og * 8 + o);
        accA[o] = pk2(bv, bv); accB[o] = pk2(bv, bv);
    }

#pragma unroll 2
    for (int c = 0; c < CM; c++) {
        u64 aqA = ap[c * 64 + lane];
        u64 aqB = ap[c * 64 + 32 + lane];
        const u64* wr = wp + c * KCH + og * 8;
#pragma unroll
        for (int o = 0; o < 8; o++) {
            u64 wv = wr[o];
            fma2(accA[o], wv, aqA);
            fma2(accB[o], wv, aqB);
        }
    }

    int kk0 = og * 8;
    int g0 = kk0 / 27;
    int brk = (g0 + 1) * 27 - kk0;       // o < brk -> group g0, else g0+1
    float su0 = 0.f, sq0 = 0.f, su1 = 0.f, sq1 = 0.f;
#pragma unroll
    for (int o = 0; o < 8; o++) {
        int kk = kk0 + o;
        float* dst = g_wk + (b * KCH + kk) * S + s;
        *(u64*)(dst + 2 * lane) = accA[o];
        *(u64*)(dst + 64 + 2 * lane) = accB[o];
        float a0, b0, a1, b1;
        upk2(accA[o], a0, b0); upk2(accB[o], a1, b1);
        float ss = a0 + b0 + a1 + b1;
        float qq = a0 * a0 + b0 * b0 + a1 * a1 + b1 * b1;
        if (o < brk) { su0 += ss; sq0 += qq; } else { su1 += ss; sq1 += qq; }
    }
#pragma unroll
    for (int off = 16; off; off >>= 1) {
        su0 += __shfl_down_sync(0xffffffffu, su0, off);
        sq0 += __shfl_down_sync(0xffffffffu, sq0, off);
        su1 += __shfl_down_sync(0xffffffffu, su1, off);
        sq1 += __shfl_down_sync(0xffffffffu, sq1, off);
    }
    if (lane == 0) {
        atomicAdd(&redsum[g0], su0); atomicAdd(&redsq[g0], sq0);
        if (brk < 8) { atomicAdd(&redsum[g0 + 1], su1); atomicAdd(&redsq[g0 + 1], sq1); }
    }
    __syncthreads();
    if (t < NG) {
        atomicAdd(&g_sum[b * NG + t], redsum[t]);
        atomicAdd(&g_sq [b * NG + t], redsq[t]);
    }
}

// ---------------- k4: finalize GN stats, then reset accumulators ----------------
__global__ void k4_stats() {
    int i = threadIdx.x;
    if (i < NB * NG) {
        float n  = 27.f * (float)S;
        float mu = g_sum[i] / n;
        float var = g_sq[i] / n - mu * mu;
        g_mu[i] = mu;
        g_rstd[i] = rsqrtf(var + 1e-5f);
        g_sum[i] = 0.f;          // restore zero-invariant for next call
        g_sq[i]  = 0.f;
    }
}

// ---------------- k5: GN affine + SKA (circular) + BN + residual -> y ------
// v2: taps processed in 3 d-groups so only 9 kv pairs (18 u64) are live at a
// time (was 54 u64 -> register blowup / low occupancy). FMA order per
// accumulator is unchanged (k = 0..26), so arithmetic is bitwise identical.
__global__ void __launch_bounds__(128) k5_ska(
        const float* __restrict__ x,
        const float* __restrict__ gn_g, const float* __restrict__ gn_b,
        const float* __restrict__ bn_s, const float* __restrict__ bn_b) {
    int gid = blockIdx.x * blockDim.x + threadIdx.x;   // 0 .. 131071
    int wq = gid & 7;
    int h  = (gid >> 3) & 31;
    int d  = (gid >> 8) & 31;
    int g  = (gid >> 13) & 7;
    int b  = gid >> 16;
    int w0 = wq * 4;
    int sbase = (d * 32 + h) * 32 + w0;

    float mu = g_mu[b * NG + g], rs = g_rstd[b * NG + g];

    u64 accL[CPG], accH[CPG];
#pragma unroll
    for (int c = 0; c < CPG; c++) { accL[c] = 0ull; accH[c] = 0ull; }

    const float* xg = x + (b * CIN + g * CPG) * S;
    const float* wsrc = g_wk + (b * KCH + g * 27) * S + sbase;

    for (int dgi = 0; dgi < 3; dgi++) {
        int zd = (d + dgi - 1) & 31;

        // kv for the 9 taps of this d-plane, GN-affined, packed
        u64 kvL[9], kvH[9];
#pragma unroll
        for (int j = 0; j < 9; j++) {
            int k = dgi * 9 + j;
            float4 q = *(const float4*)(wsrc + k * S);
            int ch = g * 27 + k;
            float gg = __ldg(gn_g + ch) * rs;
            float bb = __ldg(gn_b + ch) - mu * gg;
            kvL[j] = pk2(q.x * gg + bb, q.y * gg + bb);
            kvH[j] = pk2(q.z * gg + bb, q.w * gg + bb);
        }

#pragma unroll
        for (int c = 0; c < CPG; c++) {
            const float* xc = xg + c * S;
#pragma unroll
            for (int hi = 0; hi < 3; hi++) {
                int zh = (h + hi - 1) & 31;
                const float* row = xc + (zd * 32 + zh) * 32;
                float4 mid = *(const float4*)(row + w0);
                float v0 = row[(w0 - 1) & 31];
                float v5 = row[(w0 + 4) & 31];
                u64 p01 = pk2(v0,    mid.x);
                u64 p12 = pk2(mid.x, mid.y);
                u64 p23 = pk2(mid.y, mid.z);
                u64 p34 = pk2(mid.z, mid.w);
                u64 p45 = pk2(mid.w, v5);
                int j = hi * 3;
                fma2(accL[c], kvL[j + 0], p01);
                fma2(accL[c], kvL[j + 1], p12);
                fma2(accL[c], kvL[j + 2], p23);
                fma2(accH[c], kvH[j + 0], p23);
                fma2(accH[c], kvH[j + 1], p34);
                fma2(accH[c], kvH[j + 2], p45);
            }
        }
    }

    float* yg = g_y + (b * CIN + g * CPG) * S;
#pragma unroll
    for (int c = 0; c < CPG; c++) {
        float a0, a1v, a2v, a3v;
        upk2(accL[c], a0, a1v); upk2(accH[c], a2v, a3v);
        int ch = g * CPG + c;
        float bs_ = __ldg(bn_s + ch), bb_ = __ldg(bn_b + ch);
        float4 xq = *(const float4*)(xg + c * S + sbase);
        float4 r;
        r.x = a0  * bs_ + bb_ + xq.x;
        r.y = a1v * bs_ + bb_ + xq.y;
        r.z = a2v * bs_ + bb_ + xq.z;
        r.w = a3v * bs_ + bb_ + xq.w;
        *(float4*)(yg + c * S + sbase) = r;
    }
}

// ---------------- k6a: pw1 (64->128) + BN + ReLU ----------------
// block 256 = 8 warps, warp = og (16 outs); thread = 2 pair-slots.
__global__ void __launch_bounds__(256) k6a_pw1(
        const float* __restrict__ w, const float* __restrict__ sc,
        const float* __restrict__ bi) {
    extern __shared__ u64 sm[];
    u64* wp = sm;              // [c][128] = 8192 u64 = 64KB
    int t = threadIdx.x;
    for (int i = t; i < 8192; i += 256) {
        int c = i >> 7, o = i & 127;
        float v = w[o * 64 + c];
        wp[i] = pk2(v, v);
    }
    __syncthreads();

    int og = t >> 5, lane = t & 31;     // og 0..7
    int pos0 = blockIdx.x * 128;        // grid 512
    int b = pos0 >> 15, s = pos0 & (S - 1);

    u64 accA[16], accB[16];
#pragma unroll
    for (int o = 0; o < 16; o++) { accA[o] = 0ull; accB[o] = 0ull; }

    const float* yb = g_y + b * CIN * S + s;
#pragma unroll 2
    for (int c = 0; c < CIN; c++) {
        const float* yr = yb + c * S;
        u64 yqA = *(const u64*)(yr + 2 * lane);
        u64 yqB = *(const u64*)(yr + 64 + 2 * lane);
        const u64* wr = wp + c * 128 + og * 16;
#pragma unroll
        for (int o = 0; o < 16; o++) {
            fma2(accA[o], wr[o], yqA);
            fma2(accB[o], wr[o], yqB);
        }
    }
#pragma unroll
    for (int o = 0; o < 16; o++) {
        int oo = og * 16 + o;
        float scv = __ldg(sc + oo), biv = __ldg(bi + oo);
        float a, bq;
        float* hb = g_h + (b * 128 + oo) * S + s;
        upk2(accA[o], a, bq);
        *(u64*)(hb + 2 * lane) = pk2(fmaxf(a * scv + biv, 0.f), fmaxf(bq * scv + biv, 0.f));
        upk2(accB[o], a, bq);
        *(u64*)(hb + 64 + 2 * lane) = pk2(fmaxf(a * scv + biv, 0.f), fmaxf(bq * scv + biv, 0.f));
    }
}

// ---------------- k6b: pw2 (128->64) + BN + add y -> out ----------------
// block 256 = 8 warps: og = warp&3 (16 outs), pset = warp>>2; 256 pos/block.
__global__ void __launch_bounds__(256) k6b_pw2(
        const float* __restrict__ w, const float* __restrict__ sc,
        const float* __restrict__ bi, float* __restrict__ out) {
    extern __shared__ u64 sm[];
    u64* wp = sm;              // [c][64] = 8192 u64 = 64KB
    int t = threadIdx.x;
    for (int i = t; i < 8192; i += 256) {
        int c = i >> 6, o = i & 63;
        float v = w[o * 128 + c];
        wp[i] = pk2(v, v);
    }
    __syncthreads();

    int warp = t >> 5, lane = t & 31;
    int og = warp & 3, pset = warp >> 2;      // og 0..3, pset 0..1
    int p0 = pset * 64 + lane;                // pairs p0, p0+32
    int pos0 = blockIdx.x * 256;              // grid 256
    int b = pos0 >> 15, s = pos0 & (S - 1);

    u64 accA[16], accB[16];
#pragma unroll
    for (int o = 0; o < 16; o++) { accA[o] = 0ull; accB[o] = 0ull; }

    const float* hb = g_h + b * 128 * S + s;
#pragma unroll 2
    for (int c = 0; c < 128; c++) {
        const float* hr = hb + c * S;
        u64 hqA = *(const u64*)(hr + 2 * p0);
        u64 hqB = *(const u64*)(hr + 2 * p0 + 64);
        const u64* wr = wp + c * 64 + og * 16;
#pragma unroll
        for (int o = 0; o < 16; o++) {
            fma2(accA[o], wr[o], hqA);
            fma2(accB[o], wr[o], hqB);
        }
    }
#pragma unroll
    for (int o = 0; o < 16; o++) {
        int oo = og * 16 + o;
        float scv = __ldg(sc + oo), biv = __ldg(bi + oo);
        const float* yb = g_y + (b * CIN + oo) * S + s;
        float* ob = out + (b * CIN + oo) * S + s;
        float a, bq, y0, y1;
        upk2(accA[o], a, bq);
        upk2(*(const u64*)(yb + 2 * p0), y0, y1);
        *(u64*)(ob + 2 * p0) = pk2(y0 + a * scv + biv, y1 + bq * scv + biv);
        upk2(accB[o], a, bq);
        upk2(*(const u64*)(yb + 2 * p0 + 64), y0, y1);
        *(u64*)(ob + 2 * p0 + 64) = pk2(y0 + a * scv + biv, y1 + bq * scv + biv);
    }
}

// ---------------- launcher ----------------
extern "C" void kernel_launch(void* const* d_in, const int* in_sizes, int n_in,
                              void* d_out, int out_size) {
    const float* x     = (const float*)d_in[0];
    const float* w1    = (const float*)d_in[1];
    const float* s1    = (const float*)d_in[2];
    const float* b1    = (const float*)d_in[3];
    const float* w2    = (const float*)d_in[4];
    const float* s2    = (const float*)d_in[5];
    const float* b2    = (const float*)d_in[6];
    const float* w3    = (const float*)d_in[7];
    const float* s3    = (const float*)d_in[8];
    const float* b3    = (const float*)d_in[9];
    const float* w4    = (const float*)d_in[10];
    const float* b4    = (const float*)d_in[11];
    const float* gn_g  = (const float*)d_in[12];
    const float* gn_b  = (const float*)d_in[13];
    const float* bn_s  = (const float*)d_in[14];
    const float* bn_b  = (const float*)d_in[15];
    const float* pw1_w = (const float*)d_in[16];
    const float* pw1_s = (const float*)d_in[17];
    const float* pw1_b = (const float*)d_in[18];
    const float* pw2_w = (const float*)d_in[19];
    const float* pw2_s = (const float*)d_in[20];
    const float* pw2_b = (const float*)d_in[21];
    float* out = (float*)d_out;

    const int smem_k3b = (KCH * CM + 2048) * 8;      // 70 KB
    const int smem_k6  = 8192 * 8;                   // 64 KB
    cudaFuncSetAttribute(k3b_cv4, cudaFuncAttributeMaxDynamicSharedMemorySize, smem_k3b);
    cudaFuncSetAttribute(k6a_pw1, cudaFuncAttributeMaxDynamicSharedMemorySize, smem_k6);
    cudaFuncSetAttribute(k6b_pw2, cudaFuncAttributeMaxDynamicSharedMemorySize, smem_k6);

    k1_cv1  <<<128, 256>>>(x, w1, s1, b1);           // 512 pos/block
    k2_dw5  <<<2048, 128>>>(w2, s2, b2);
    k3a_cv3 <<<128, 256>>>(w3, s3, b3);
    k3b_cv4 <<<512, 864, smem_k3b>>>(w4, b4);
    k4_stats<<<1, 32>>>();
    k5_ska  <<<1024, 128>>>(x, gn_g, gn_b, bn_s, bn_b);  // v2, low-reg
    k6a_pw1 <<<512, 256, smem_k6>>>(pw1_w, pw1_s, pw1_b);
    k6b_pw2 <<<256, 256, smem_k6>>>(pw2_w, pw2_s, pw2_b, out);
}

// round 11
// speedup vs baseline: 1.2920x; 1.0767x over previous
#include <cuda_runtime.h>

#define S   32768          // 32*32*32 spatial
#define NB  2              // batch
#define CIN 64
#define CM  32             // mid channels
#define KCH 216            // dynamic kernel channels
#define NG  8              // groups
#define CPG 8              // channels per group (64/8)

typedef unsigned long long u64;

// ---------------- f32x2 helpers ----------------
__device__ __forceinline__ u64 pk2(float a, float b) {
    u64 r; asm("mov.b64 %0,{%1,%2};" : "=l"(r) : "f"(a), "f"(b)); return r;
}
__device__ __forceinline__ void upk2(u64 v, float& a, float& b) {
    asm("mov.b64 {%0,%1},%2;" : "=f"(a), "=f"(b) : "l"(v));
}
__device__ __forceinline__ void fma2(u64& d, u64 a, u64 b) {
    asm("fma.rn.f32x2 %0,%1,%2,%0;" : "+l"(d) : "l"(a), "l"(b));
}

// ---------------- scratch (device globals; allocation-free) ----------------
__device__ float g_a1[NB * CM  * S];   // cv1 out; later reused for cv3 out (a3)
__device__ float g_a2[NB * CM  * S];   // after dw5+bn
__device__ float g_wk[NB * KCH * S];   // cv4 output (pre-GN)
__device__ float g_y [NB * CIN * S];   // after SKA + bn + residual
__device__ float g_h [NB * 128 * S];   // FFN hidden
__device__ float g_sum[NB * NG];       // zero-init; k4 re-zeros after use
__device__ float g_sq [NB * NG];
__device__ float g_mu [NB * NG];
__device__ float g_rstd[NB * NG];

// ---------------- cv body: K->32 1x1 conv + BN + ReLU (R10 passing) ----------
template<int K>
__device__ __forceinline__ void cv_body(
        const float* __restrict__ in, const float* __restrict__ w,
        const float* __restrict__ sc, const float* __restrict__ bi,
        float* __restrict__ outbuf) {
    __shared__ u64 ws[K * 32];       // [c][o]
    int t = threadIdx.x;
    for (int i = t; i < K * 32; i += 256) {
        int c = i >> 5, o = i & 31;
        float v = w[o * K + c];
        ws[i] = pk2(v, v);
    }
    __syncthreads();

    int warp = t >> 5, lane = t & 31;
    int og = warp & 1, pset = warp >> 1;
    int pr = pset * 32 + lane;
    int pos0 = blockIdx.x * 512;
    int b = pos0 >> 15, s = pos0 & (S - 1);
    int sA = s + 2 * pr;
    int sB = sA + 256;

    u64 accA[16], accB[16];
#pragma unroll
    for (int o = 0; o < 16; o++) { accA[o] = 0ull; accB[o] = 0ull; }

    const float* ib = in + b * K * S;
#pragma unroll 2
    for (int c = 0; c < K; c++) {
        u64 xqA = *(const u64*)(ib + c * S + sA);
        u64 xqB = *(const u64*)(ib + c * S + sB);
        const u64* wr = ws + c * 32 + og * 16;
#pragma unroll
        for (int o = 0; o < 16; o++) {
            u64 wv = wr[o];
            fma2(accA[o], wv, xqA);
            fma2(accB[o], wv, xqB);
        }
    }
#pragma unroll
    for (int o = 0; o < 16; o++) {
        int oo = og * 16 + o;
        float scv = __ldg(sc + oo), biv = __ldg(bi + oo);
        float a, bq;
        float* ob = outbuf + (b * CM + oo) * S;
        upk2(accA[o], a, bq);
        *(u64*)(ob + sA) = pk2(fmaxf(a * scv + biv, 0.f), fmaxf(bq * scv + biv, 0.f));
        upk2(accB[o], a, bq);
        *(u64*)(ob + sB) = pk2(fmaxf(a * scv + biv, 0.f), fmaxf(bq * scv + biv, 0.f));
    }
}

__global__ void __launch_bounds__(256) k1_cv1(
        const float* __restrict__ x, const float* __restrict__ w1,
        const float* __restrict__ s1, const float* __restrict__ b1) {
    cv_body<64>(x, w1, s1, b1, g_a1);
}

__global__ void __launch_bounds__(256) k3a_cv3(
        const float* __restrict__ w3, const float* __restrict__ s3,
        const float* __restrict__ b3) {
    cv_body<32>(g_a2, w3, s3, b3, g_a1);
}

// ---------------- k2: depthwise 5x5x5 (zero pad) + BN, f32x2 (R10 passing) ---
__global__ void __launch_bounds__(128) k2_dw5(
        const float* __restrict__ w2, const float* __restrict__ s2,
        const float* __restrict__ b2) {
    int blk = blockIdx.x;
    int d = blk & 31;
    int c = (blk >> 5) & 31;
    int b = blk >> 10;
    int t = threadIdx.x;
    int wq = t & 3, h = t >> 2;
    int w0 = wq * 8;

    const float* src = g_a1 + (b * CM + c) * S;
    const float* wc  = w2 + c * 125;
    const float4 zero4 = make_float4(0.f, 0.f, 0.f, 0.f);

    u64 acc[4];
#pragma unroll
    for (int m = 0; m < 4; m++) acc[m] = 0ull;

    for (int dd = 0; dd < 5; dd++) {
        int zd = d + dd - 2;
        if ((unsigned)zd >= 32u) continue;
        for (int dh = 0; dh < 5; dh++) {
            int zh = h + dh - 2;
            if ((unsigned)zh >= 32u) continue;
            const float* row = src + (zd * 32 + zh) * 32;
            float4 f0 = (wq > 0) ? *(const float4*)(row + w0 - 4) : zero4;
            float4 f1 = *(const float4*)(row + w0);
            float4 f2 = *(const float4*)(row + w0 + 4);
            float4 f3 = (wq < 3) ? *(const float4*)(row + w0 + 8) : zero4;
            u64 A0 = pk2(f0.z, f0.w), A1 = pk2(f1.x, f1.y), A2 = pk2(f1.z, f1.w);
            u64 A3 = pk2(f2.x, f2.y), A4 = pk2(f2.z, f2.w), A5 = pk2(f3.x, f3.y);
            u64 M0 = pk2(f0.w, f1.x), M1 = pk2(f1.y, f1.z), M2 = pk2(f1.w, f2.x);
            u64 M3 = pk2(f2.y, f2.z), M4 = pk2(f2.w, f3.x);
            const float* wr = wc + (dd * 5 + dh) * 5;
            u64 T0 = pk2(wr[0], wr[0]), T1 = pk2(wr[1], wr[1]), T2 = pk2(wr[2], wr[2]);
            u64 T3 = pk2(wr[3], wr[3]), T4 = pk2(wr[4], wr[4]);
            fma2(acc[0], T0, A0); fma2(acc[0], T1, M0); fma2(acc[0], T2, A1);
            fma2(acc[0], T3, M1); fma2(acc[0], T4, A2);
            fma2(acc[1], T0, A1); fma2(acc[1], T1, M1); fma2(acc[1], T2, A2);
            fma2(acc[1], T3, M2); fma2(acc[1], T4, A3);
            fma2(acc[2], T0, A2); fma2(acc[2], T1, M2); fma2(acc[2], T2, A3);
            fma2(acc[2], T3, M3); fma2(acc[2], T4, A4);
            fma2(acc[3], T0, A3); fma2(acc[3], T1, M3); fma2(acc[3], T2, A4);
            fma2(acc[3], T3, M4); fma2(acc[3], T4, A5);
        }
    }
    float scv = s2[c], biv = b2[c];
    float* dst = g_a2 + (b * CM + c) * S + (d * 32 + h) * 32 + w0;
#pragma unroll
    for (int m = 0; m < 4; m++) {
        float a, bb; upk2(acc[m], a, bb);
        *(u64*)(dst + 2 * m) = pk2(a * scv + biv, bb * scv + biv);
    }
}

// ---------------- k3b: cv4 (32->216) + b4 + GN partial sums, v3 -------------
// grid = 512 spatial x 3 o-chunks (72 outs each). block 288 = 9 warps x 8 outs.
// thread = 2 pair-slots; acts ulonglong2 (one LDS.128); acts+weights
// double-buffered so LDS latency hides behind the 16-FMA window.
__global__ void __launch_bounds__(288) k3b_cv4(
        const float* __restrict__ w4, const float* __restrict__ b4) {
    extern __shared__ u64 sm[];
    u64* wp = sm;                                  // [c][72] = 2304 u64
    ulonglong2* apv = (ulonglong2*)(sm + 2304);    // [c][32] pairs (lane, lane+32)
    __shared__ float redsum[NG], redsq[NG];
    int t = threadIdx.x;
    int oc = blockIdx.x % 3;
    int sblk = blockIdx.x / 3;
    int kkbase = oc * 72;

    for (int i = t; i < 72 * CM; i += 288) {
        int c = i / 72, o = i - c * 72;
        float v = w4[(kkbase + o) * CM + c];
        wp[i] = pk2(v, v);
    }
    if (t < NG) { redsum[t] = 0.f; redsq[t] = 0.f; }

    int pos0 = sblk * 128;
    int b = pos0 >> 15, s = pos0 & (S - 1);
    for (int i = t; i < 1024; i += 288) {
        int c = i >> 5, ll = i & 31;
        const float* p = g_a1 + (b * CM + c) * S + s;
        ulonglong2 v;
        v.x = *(const u64*)(p + 2 * ll);
        v.y = *(const u64*)(p + 64 + 2 * ll);
        apv[i] = v;
    }
    __syncthreads();

    int warp = t >> 5, lane = t & 31;       // warp 0..8
    int kk0 = kkbase + warp * 8;

    u64 accA[8], accB[8];
#pragma unroll
    for (int o = 0; o < 8; o++) {
        float bv = __ldg(b4 + kk0 + o);
        accA[o] = pk2(bv, bv); accB[o] = pk2(bv, bv);
    }

    // pipelined mainloop
    ulonglong2 aq = apv[lane];
    u64 wc_[8];
    {
        const u64* wr = wp + warp * 8;
#pragma unroll
        for (int o = 0; o < 8; o++) wc_[o] = wr[o];
    }
#pragma unroll
    for (int c = 0; c < CM - 1; c++) {
        ulonglong2 aqn = apv[(c + 1) * 32 + lane];
        u64 wn[8];
        const u64* wr = wp + (c + 1) * 72 + warp * 8;
#pragma unroll
        for (int o = 0; o < 8; o++) wn[o] = wr[o];
#pragma unroll
        for (int o = 0; o < 8; o++) {
            fma2(accA[o], wc_[o], aq.x);
            fma2(accB[o], wc_[o], aq.y);
        }
        aq = aqn;
#pragma unroll
        for (int o = 0; o < 8; o++) wc_[o] = wn[o];
    }
#pragma unroll
    for (int o = 0; o < 8; o++) {           // last c
        fma2(accA[o], wc_[o], aq.x);
        fma2(accB[o], wc_[o], aq.y);
    }

    // store wk + per-group stats (8-out window spans at most 2 groups)
    int g0 = kk0 / 27;
    int brk = (g0 + 1) * 27 - kk0;
    float su0 = 0.f, sq0 = 0.f, su1 = 0.f, sq1 = 0.f;
#pragma unroll
    for (int o = 0; o < 8; o++) {
        int kk = kk0 + o;
        float* dst = g_wk + (b * KCH + kk) * S + s;
        *(u64*)(dst + 2 * lane) = accA[o];
        *(u64*)(dst + 64 + 2 * lane) = accB[o];
        float a0, b0, a1, b1;
        upk2(accA[o], a0, b0); upk2(accB[o], a1, b1);
        float ss = a0 + b0 + a1 + b1;
        float qq = a0 * a0 + b0 * b0 + a1 * a1 + b1 * b1;
        if (o < brk) { su0 += ss; sq0 += qq; } else { su1 += ss; sq1 += qq; }
    }
#pragma unroll
    for (int off = 16; off; off >>= 1) {
        su0 += __shfl_down_sync(0xffffffffu, su0, off);
        sq0 += __shfl_down_sync(0xffffffffu, sq0, off);
        su1 += __shfl_down_sync(0xffffffffu, su1, off);
        sq1 += __shfl_down_sync(0xffffffffu, sq1, off);
    }
    if (lane == 0) {
        atomicAdd(&redsum[g0], su0); atomicAdd(&redsq[g0], sq0);
        if (brk < 8) { atomicAdd(&redsum[g0 + 1], su1); atomicAdd(&redsq[g0 + 1], sq1); }
    }
    __syncthreads();
    if (t < NG) {
        atomicAdd(&g_sum[b * NG + t], redsum[t]);
        atomicAdd(&g_sq [b * NG + t], redsq[t]);
    }
}

// ---------------- k4: finalize GN stats, then reset accumulators ------------
__global__ void k4_stats() {
    int i = threadIdx.x;
    if (i < NB * NG) {
        float n  = 27.f * (float)S;
        float mu = g_sum[i] / n;
        float var = g_sq[i] / n - mu * mu;
        g_mu[i] = mu;
        g_rstd[i] = rsqrtf(var + 1e-5f);
        g_sum[i] = 0.f;
        g_sq[i]  = 0.f;
    }
}

// ---------------- k5: GN affine + SKA (circular) + BN + residual (R10) ------
__global__ void __launch_bounds__(128) k5_ska(
        const float* __restrict__ x,
        const float* __restrict__ gn_g, const float* __restrict__ gn_b,
        const float* __restrict__ bn_s, const float* __restrict__ bn_b) {
    int gid = blockIdx.x * blockDim.x + threadIdx.x;
    int wq = gid & 7;
    int h  = (gid >> 3) & 31;
    int d  = (gid >> 8) & 31;
    int g  = (gid >> 13) & 7;
    int b  = gid >> 16;
    int w0 = wq * 4;
    int sbase = (d * 32 + h) * 32 + w0;

    float mu = g_mu[b * NG + g], rs = g_rstd[b * NG + g];

    u64 accL[CPG], accH[CPG];
#pragma unroll
    for (int c = 0; c < CPG; c++) { accL[c] = 0ull; accH[c] = 0ull; }

    const float* xg = x + (b * CIN + g * CPG) * S;
    const float* wsrc = g_wk + (b * KCH + g * 27) * S + sbase;

    for (int dgi = 0; dgi < 3; dgi++) {
        int zd = (d + dgi - 1) & 31;
        u64 kvL[9], kvH[9];
#pragma unroll
        for (int j = 0; j < 9; j++) {
            int k = dgi * 9 + j;
            float4 q = *(const float4*)(wsrc + k * S);
            int ch = g * 27 + k;
            float gg = __ldg(gn_g + ch) * rs;
            float bb = __ldg(gn_b + ch) - mu * gg;
            kvL[j] = pk2(q.x * gg + bb, q.y * gg + bb);
            kvH[j] = pk2(q.z * gg + bb, q.w * gg + bb);
        }
#pragma unroll
        for (int c = 0; c < CPG; c++) {
            const float* xc = xg + c * S;
#pragma unroll
            for (int hi = 0; hi < 3; hi++) {
                int zh = (h + hi - 1) & 31;
                const float* row = xc + (zd * 32 + zh) * 32;
                float4 mid = *(const float4*)(row + w0);
                float v0 = row[(w0 - 1) & 31];
                float v5 = row[(w0 + 4) & 31];
                u64 p01 = pk2(v0,    mid.x);
                u64 p12 = pk2(mid.x, mid.y);
                u64 p23 = pk2(mid.y, mid.z);
                u64 p34 = pk2(mid.z, mid.w);
                u64 p45 = pk2(mid.w, v5);
                int j = hi * 3;
                fma2(accL[c], kvL[j + 0], p01);
                fma2(accL[c], kvL[j + 1], p12);
                fma2(accL[c], kvL[j + 2], p23);
                fma2(accH[c], kvH[j + 0], p23);
                fma2(accH[c], kvH[j + 1], p34);
                fma2(accH[c], kvH[j + 2], p45);
            }
        }
    }

    float* yg = g_y + (b * CIN + g * CPG) * S;
#pragma unroll
    for (int c = 0; c < CPG; c++) {
        float a0, a1v, a2v, a3v;
        upk2(accL[c], a0, a1v); upk2(accH[c], a2v, a3v);
        int ch = g * CPG + c;
        float bs_ = __ldg(bn_s + ch), bb_ = __ldg(bn_b + ch);
        float4 xq = *(const float4*)(xg + c * S + sbase);
        float4 r;
        r.x = a0  * bs_ + bb_ + xq.x;
        r.y = a1v * bs_ + bb_ + xq.y;
        r.z = a2v * bs_ + bb_ + xq.z;
        r.w = a3v * bs_ + bb_ + xq.w;
        *(float4*)(yg + c * S + sbase) = r;
    }
}

// ---------------- k6a: pw1 (64->128) + BN + ReLU, v3 (pipelined) ------------
// grid = 512 spatial x 2 o-chunks (64 outs). block 256 = 8 warps x 8 outs.
__global__ void __launch_bounds__(256) k6a_pw1(
        const float* __restrict__ w, const float* __restrict__ sc,
        const float* __restrict__ bi) {
    extern __shared__ u64 sm[];
    u64* wp = sm;                      // [c][64] chunk = 4096 u64 = 32KB
    int t = threadIdx.x;
    int oc = blockIdx.x & 1;
    int sblk = blockIdx.x >> 1;
    for (int i = t; i < 4096; i += 256) {
        int c = i >> 6, ol = i & 63;
        float v = w[(oc * 64 + ol) * 64 + c];
        wp[i] = pk2(v, v);
    }
    __syncthreads();

    int og = t >> 5, lane = t & 31;    // og 0..7
    int pos0 = sblk * 128;
    int b = pos0 >> 15, s = pos0 & (S - 1);

    u64 accA[8], accB[8];
#pragma unroll
    for (int o = 0; o < 8; o++) { accA[o] = 0ull; accB[o] = 0ull; }

    const float* yb = g_y + b * CIN * S + s;
    u64 yA = *(const u64*)(yb + 2 * lane);
    u64 yB = *(const u64*)(yb + 64 + 2 * lane);
    u64 wc_[8];
    {
        const u64* wr = wp + og * 8;
#pragma unroll
        for (int o = 0; o < 8; o++) wc_[o] = wr[o];
    }
#pragma unroll 8
    for (int c = 0; c < CIN - 1; c++) {
        const float* yr = yb + (c + 1) * S;
        u64 yAn = *(const u64*)(yr + 2 * lane);
        u64 yBn = *(const u64*)(yr + 64 + 2 * lane);
        u64 wn[8];
        const u64* wr = wp + (c + 1) * 64 + og * 8;
#pragma unroll
        for (int o = 0; o < 8; o++) wn[o] = wr[o];
#pragma unroll
        for (int o = 0; o < 8; o++) {
            fma2(accA[o], wc_[o], yA);
            fma2(accB[o], wc_[o], yB);
        }
        yA = yAn; yB = yBn;
#pragma unroll
        for (int o = 0; o < 8; o++) wc_[o] = wn[o];
    }
#pragma unroll
    for (int o = 0; o < 8; o++) {
        fma2(accA[o], wc_[o], yA);
        fma2(accB[o], wc_[o], yB);
    }

#pragma unroll
    for (int o = 0; o < 8; o++) {
        int oo = oc * 64 + og * 8 + o;
        float scv = __ldg(sc + oo), biv = __ldg(bi + oo);
        float a, bq;
        float* hb = g_h + (b * 128 + oo) * S + s;
        upk2(accA[o], a, bq);
        *(u64*)(hb + 2 * lane) = pk2(fmaxf(a * scv + biv, 0.f), fmaxf(bq * scv + biv, 0.f));
        upk2(accB[o], a, bq);
        *(u64*)(hb + 64 + 2 * lane) = pk2(fmaxf(a * scv + biv, 0.f), fmaxf(bq * scv + biv, 0.f));
    }
}

// ---------------- k6b: pw2 (128->64) + BN + add y -> out, v3 (pipelined) ----
// grid = 512 spatial blocks (128 pos). block 256 = 8 warps x 8 outs.
__global__ void __launch_bounds__(256) k6b_pw2(
        const float* __restrict__ w, const float* __restrict__ sc,
        const float* __restrict__ bi, float* __restrict__ out) {
    extern __shared__ u64 sm[];
    u64* wp = sm;                      // [c][64] = 8192 u64 = 64KB
    int t = threadIdx.x;
    for (int i = t; i < 8192; i += 256) {
        int c = i >> 6, o = i & 63;
        float v = w[o * 128 + c];      // pw2_w [64][128] row-major
        wp[i] = pk2(v, v);
    }
    __syncthreads();

    int og = t >> 5, lane = t & 31;    // og 0..7
    int pos0 = blockIdx.x * 128;
    int b = pos0 >> 15, s = pos0 & (S - 1);

    u64 accA[8], accB[8];
#pragma unroll
    for (int o = 0; o < 8; o++) { accA[o] = 0ull; accB[o] = 0ull; }

    const float* hb = g_h + b * 128 * S + s;
    u64 hA = *(const u64*)(hb + 2 * lane);
    u64 hB = *(const u64*)(hb + 64 + 2 * lane);
    u64 wc_[8];
    {
        const u64* wr = wp + og * 8;
#pragma unroll
        for (int o = 0; o < 8; o++) wc_[o] = wr[o];
    }
#pragma unroll 8
    for (int c = 0; c < 127; c++) {
        const float* hr = hb + (c + 1) * S;
        u64 hAn = *(const u64*)(hr + 2 * lane);
        u64 hBn = *(const u64*)(hr + 64 + 2 * lane);
        u64 wn[8];
        const u64* wr = wp + (c + 1) * 64 + og * 8;
#pragma unroll
        for (int o = 0; o < 8; o++) wn[o] = wr[o];
#pragma unroll
        for (int o = 0; o < 8; o++) {
            fma2(accA[o], wc_[o], hA);
            fma2(accB[o], wc_[o], hB);
        }
        hA = hAn; hB = hBn;
#pragma unroll
        for (int o = 0; o < 8; o++) wc_[o] = wn[o];
    }
#pragma unroll
    for (int o = 0; o < 8; o++) {
        fma2(accA[o], wc_[o], hA);
        fma2(accB[o], wc_[o], hB);
    }

#pragma unroll
    for (int o = 0; o < 8; o++) {
        int oo = og * 8 + o;
        float scv = __ldg(sc + oo), biv = __ldg(bi + oo);
        const float* yb = g_y + (b * CIN + oo) * S + s;
        float* ob = out + (b * CIN + oo) * S + s;
        float a, bq, y0, y1;
        upk2(accA[o], a, bq);
        upk2(*(const u64*)(yb + 2 * lane), y0, y1);
        *(u64*)(ob + 2 * lane) = pk2(y0 + a * scv + biv, y1 + bq * scv + biv);
        upk2(accB[o], a, bq);
        upk2(*(const u64*)(yb + 64 + 2 * lane), y0, y1);
        *(u64*)(ob + 64 + 2 * lane) = pk2(y0 + a * scv + biv, y1 + bq * scv + biv);
    }
}

// ---------------- launcher ----------------
extern "C" void kernel_launch(void* const* d_in, const int* in_sizes, int n_in,
                              void* d_out, int out_size) {
    const float* x     = (const float*)d_in[0];
    const float* w1    = (const float*)d_in[1];
    const float* s1    = (const float*)d_in[2];
    const float* b1    = (const float*)d_in[3];
    const float* w2    = (const float*)d_in[4];
    const float* s2    = (const float*)d_in[5];
    const float* b2    = (const float*)d_in[6];
    const float* w3    = (const float*)d_in[7];
    const float* s3    = (const float*)d_in[8];
    const float* b3    = (const float*)d_in[9];
    const float* w4    = (const float*)d_in[10];
    const float* b4    = (const float*)d_in[11];
    const float* gn_g  = (const float*)d_in[12];
    const float* gn_b  = (const float*)d_in[13];
    const float* bn_s  = (const float*)d_in[14];
    const float* bn_b  = (const float*)d_in[15];
    const float* pw1_w = (const float*)d_in[16];
    const float* pw1_s = (const float*)d_in[17];
    const float* pw1_b = (const float*)d_in[18];
    const float* pw2_w = (const float*)d_in[19];
    const float* pw2_s = (const float*)d_in[20];
    const float* pw2_b = (const float*)d_in[21];
    float* out = (float*)d_out;

    const int smem_k3b = (2304 + 2048) * 8;          // 34 KB
    const int smem_k6a = 4096 * 8;                   // 32 KB
    const int smem_k6b = 8192 * 8;                   // 64 KB
    cudaFuncSetAttribute(k3b_cv4, cudaFuncAttributeMaxDynamicSharedMemorySize, smem_k3b);
    cudaFuncSetAttribute(k6a_pw1, cudaFuncAttributeMaxDynamicSharedMemorySize, smem_k6a);
    cudaFuncSetAttribute(k6b_pw2, cudaFuncAttributeMaxDynamicSharedMemorySize, smem_k6b);

    k1_cv1  <<<128, 256>>>(x, w1, s1, b1);
    k2_dw5  <<<2048, 128>>>(w2, s2, b2);
    k3a_cv3 <<<128, 256>>>(w3, s3, b3);
    k3b_cv4 <<<1536, 288, smem_k3b>>>(w4, b4);       // slot 3 <- profiled
    k4_stats<<<1, 32>>>();
    k5_ska  <<<1024, 128>>>(x, gn_g, gn_b, bn_s, bn_b);
    k6a_pw1 <<<1024, 256, smem_k6a>>>(pw1_w, pw1_s, pw1_b);
    k6b_pw2 <<<512, 256, smem_k6b>>>(pw2_w, pw2_s, pw2_b, out);
}